// round 4
// baseline (speedup 1.0000x reference)
#include <cuda_runtime.h>
#include <math.h>
#include <stdint.h>

// Problem constants
constexpr int Bb   = 2;
constexpr int Ss   = 1024;
constexpr int Hh   = 4096;
constexpr int NHq  = 32;
constexpr int NKVh = 8;
constexpr int HDd  = 128;
constexpr int MTOK = Bb * Ss;             // 2048
constexpr int QD   = NHq * HDd;           // 4096
constexpr int KVD  = NKVh * HDd;          // 1024

// ---------------- device scratch (static; allocation-free) ----------------
__device__ float  g_q[(size_t)MTOK * QD];        // 32 MB
__device__ float  g_k[(size_t)MTOK * KVD];       // 8 MB
__device__ float  g_v[(size_t)MTOK * KVD];       // 8 MB
__device__ float  g_attn[(size_t)MTOK * QD];     // 32 MB
__device__ float  g_scores[(size_t)Bb * NHq * Ss * Ss];  // 256 MB
__device__ int8_t g_wq[(size_t)QD * Hh];
__device__ int8_t g_wk[(size_t)KVD * Hh];
__device__ int8_t g_wv[(size_t)KVD * Hh];
__device__ int8_t g_wo[(size_t)Hh * QD];
__device__ double g_absum[4];
__device__ float  g_gamma[4];

// ---------------- gamma: abs-sum reduction ----------------
__global__ void init_kernel() {
    if (threadIdx.x < 4) g_absum[threadIdx.x] = 0.0;
}

__global__ void abssum_kernel(const float* __restrict__ w, size_t n, int idx) {
    float s = 0.f;
    for (size_t i = (size_t)blockIdx.x * blockDim.x + threadIdx.x; i < n;
         i += (size_t)gridDim.x * blockDim.x)
        s += fabsf(w[i]);
    __shared__ double sh[256];
    sh[threadIdx.x] = (double)s;
    __syncthreads();
    for (int o = 128; o > 0; o >>= 1) {
        if ((int)threadIdx.x < o) sh[threadIdx.x] += sh[threadIdx.x + o];
        __syncthreads();
    }
    if (threadIdx.x == 0) atomicAdd(&g_absum[idx], sh[0]);
}

// ---------------- ternary quantization ----------------
__global__ void quantize_kernel(const float* __restrict__ w, int8_t* __restrict__ t,
                                size_t n, int idx) {
    float gamma = (float)(g_absum[idx] / (double)n) + 1e-5f;
    if (blockIdx.x == 0 && threadIdx.x == 0) g_gamma[idx] = gamma;
    for (size_t i = (size_t)blockIdx.x * blockDim.x + threadIdx.x; i < n;
         i += (size_t)gridDim.x * blockDim.x) {
        float r = rintf(w[i] / gamma);   // round-half-even, true division like ref
        r = fminf(1.f, fmaxf(-1.f, r));
        t[i] = (int8_t)r;
    }
}

// ---------------- GEMM: C[M,N] = gamma * A[M,K] . T[N,K]^T (NT, ternary B) ----------------
__global__ __launch_bounds__(256) void gemm_nt_ternary(
    const float* __restrict__ A, const int8_t* __restrict__ T,
    float* __restrict__ C, int N, int K, int gidx)
{
    __shared__ __align__(16) float As[16][128];
    __shared__ __align__(16) float Bs[16][128];
    const int tid = threadIdx.x;
    const int m0 = blockIdx.y * 128;
    const int n0 = blockIdx.x * 128;
    const int ty = tid >> 4, tx = tid & 15;

    float acc[8][8];
#pragma unroll
    for (int i = 0; i < 8; i++)
#pragma unroll
        for (int j = 0; j < 8; j++) acc[i][j] = 0.f;

    for (int k0 = 0; k0 < K; k0 += 16) {
#pragma unroll
        for (int i = 0; i < 2; i++) {
            int idx = tid * 2 + i;
            int r = idx >> 2, c4 = idx & 3;
            float4 v = *(const float4*)(A + (size_t)(m0 + r) * K + k0 + c4 * 4);
            As[c4 * 4 + 0][r] = v.x; As[c4 * 4 + 1][r] = v.y;
            As[c4 * 4 + 2][r] = v.z; As[c4 * 4 + 3][r] = v.w;
        }
        if (tid < 128) {
            int4 p = *(const int4*)(T + (size_t)(n0 + tid) * K + k0);
            // CRITICAL: aarch64 plain `char` is UNSIGNED. Use signed char so
            // ternary -1 bytes decode to -1.0f, not +255.0f.
            const signed char* pb = reinterpret_cast<const signed char*>(&p);
#pragma unroll
            for (int kk = 0; kk < 16; kk++) Bs[kk][tid] = (float)pb[kk];
        }
        __syncthreads();
#pragma unroll
        for (int kk = 0; kk < 16; kk++) {
            float a[8], b[8];
#pragma unroll
            for (int i = 0; i < 8; i++) a[i] = As[kk][ty * 8 + i];
#pragma unroll
            for (int j = 0; j < 8; j++) b[j] = Bs[kk][tx * 8 + j];
#pragma unroll
            for (int i = 0; i < 8; i++)
#pragma unroll
                for (int j = 0; j < 8; j++) acc[i][j] = fmaf(a[i], b[j], acc[i][j]);
        }
        __syncthreads();
    }
    const float gamma = g_gamma[gidx];
#pragma unroll
    for (int i = 0; i < 8; i++) {
        size_t row = (size_t)(m0 + ty * 8 + i) * N + n0 + tx * 8;
#pragma unroll
        for (int j = 0; j < 8; j += 4) {
            float4 v = make_float4(acc[i][j] * gamma, acc[i][j + 1] * gamma,
                                   acc[i][j + 2] * gamma, acc[i][j + 3] * gamma);
            *(float4*)(C + row + j) = v;
        }
    }
}

// ---------------- RoPE (in place), uses position_ids ----------------
__global__ void rope_kernel(float* __restrict__ x, int nheads,
                            const int* __restrict__ pos_ids) {
    size_t idx = (size_t)blockIdx.x * blockDim.x + threadIdx.x;
    size_t total = (size_t)MTOK * nheads * 64;
    if (idx >= total) return;
    int d = (int)(idx & 63);                 // pair index 0..63
    size_t th = idx >> 6;
    int head = (int)(th % nheads);
    size_t tok = th / nheads;                // tok = b*S + s
    int pos = pos_ids[tok];
    float inv_freq = 1.0f / powf(10000.0f, (float)d * (1.0f / 64.0f));
    float fr = (float)pos * inv_freq;
    float s, c;
    sincosf(fr, &s, &c);
    float* base = x + tok * ((size_t)nheads * HDd) + (size_t)head * HDd;
    float x1 = base[d], x2 = base[d + 64];
    base[d]      = x1 * c - x2 * s;
    base[d + 64] = x2 * c + x1 * s;
}

// ---------------- scores: S[bh,m,n] = (q.k)/sqrt(HD), causal lower-tri only ----------------
__global__ __launch_bounds__(256) void scores_kernel() {
    const int bh = blockIdx.z;
    const int b = bh >> 5, h = bh & 31;
    const int kvh = h >> 2;
    const int m0 = blockIdx.y * 128;
    const int n0 = blockIdx.x * 128;
    if (n0 > m0) return;   // block fully above diagonal

    const float* __restrict__ A  = g_q + (size_t)b * Ss * QD  + (size_t)h * HDd;   // lda=QD
    const float* __restrict__ Bk = g_k + (size_t)b * Ss * KVD + (size_t)kvh * HDd; // ldb=KVD
    float* __restrict__ C = g_scores + (size_t)bh * Ss * Ss;

    __shared__ __align__(16) float As[16][128];
    __shared__ __align__(16) float Bs[16][128];
    const int tid = threadIdx.x;
    const int ty = tid >> 4, tx = tid & 15;

    float acc[8][8];
#pragma unroll
    for (int i = 0; i < 8; i++)
#pragma unroll
        for (int j = 0; j < 8; j++) acc[i][j] = 0.f;

    for (int k0 = 0; k0 < HDd; k0 += 16) {
#pragma unroll
        for (int i = 0; i < 2; i++) {
            int idx = tid * 2 + i;
            int r = idx >> 2, c4 = idx & 3;
            float4 va = *(const float4*)(A + (size_t)(m0 + r) * QD + k0 + c4 * 4);
            As[c4 * 4 + 0][r] = va.x; As[c4 * 4 + 1][r] = va.y;
            As[c4 * 4 + 2][r] = va.z; As[c4 * 4 + 3][r] = va.w;
            float4 vb = *(const float4*)(Bk + (size_t)(n0 + r) * KVD + k0 + c4 * 4);
            Bs[c4 * 4 + 0][r] = vb.x; Bs[c4 * 4 + 1][r] = vb.y;
            Bs[c4 * 4 + 2][r] = vb.z; Bs[c4 * 4 + 3][r] = vb.w;
        }
        __syncthreads();
#pragma unroll
        for (int kk = 0; kk < 16; kk++) {
            float a[8], bfrag[8];
#pragma unroll
            for (int i = 0; i < 8; i++) a[i] = As[kk][ty * 8 + i];
#pragma unroll
            for (int j = 0; j < 8; j++) bfrag[j] = Bs[kk][tx * 8 + j];
#pragma unroll
            for (int i = 0; i < 8; i++)
#pragma unroll
                for (int j = 0; j < 8; j++) acc[i][j] = fmaf(a[i], bfrag[j], acc[i][j]);
        }
        __syncthreads();
    }
    const float scale = 0.08838834764831845f;  // 1/sqrt(128)
#pragma unroll
    for (int i = 0; i < 8; i++) {
        int m = m0 + ty * 8 + i;
#pragma unroll
        for (int j = 0; j < 8; j++) {
            int n = n0 + tx * 8 + j;
            if (n <= m) C[(size_t)m * Ss + n] = acc[i][j] * scale;
        }
    }
}

// ---------------- row softmax over j<=i, zero-fill j>i ----------------
__global__ void softmax_kernel() {
    const int row = blockIdx.x;           // bh*1024 + i
    const int i = row & (Ss - 1);
    float* __restrict__ p = g_scores + (size_t)row * Ss;
    __shared__ float buf[Ss];
    __shared__ float red[40];
    const int len = i + 1;

    float mx = -INFINITY;
    for (int j = threadIdx.x; j < len; j += blockDim.x) {
        float v = p[j]; buf[j] = v; mx = fmaxf(mx, v);
    }
#pragma unroll
    for (int o = 16; o; o >>= 1) mx = fmaxf(mx, __shfl_xor_sync(0xffffffffu, mx, o));
    if ((threadIdx.x & 31) == 0) red[threadIdx.x >> 5] = mx;
    __syncthreads();
    if (threadIdx.x == 0) {
        float m = red[0];
        for (int w = 1; w < 8; w++) m = fmaxf(m, red[w]);
        red[32] = m;
    }
    __syncthreads();
    mx = red[32];

    float sum = 0.f;
    for (int j = threadIdx.x; j < len; j += blockDim.x) {
        float e = expf(buf[j] - mx); buf[j] = e; sum += e;
    }
#pragma unroll
    for (int o = 16; o; o >>= 1) sum += __shfl_xor_sync(0xffffffffu, sum, o);
    __syncthreads();
    if ((threadIdx.x & 31) == 0) red[threadIdx.x >> 5] = sum;
    __syncthreads();
    if (threadIdx.x == 0) {
        float s = red[0];
        for (int w = 1; w < 8; w++) s += red[w];
        red[33] = s;
    }
    __syncthreads();
    const float inv = 1.f / red[33];
    for (int j = threadIdx.x; j < Ss; j += blockDim.x)
        p[j] = (j < len) ? buf[j] * inv : 0.f;
}

// ---------------- PV: attn[b,i,h,:] = P[bh,i,:] @ V (NN GEMM, causal K-limit) ----------------
__global__ __launch_bounds__(256) void pv_kernel() {
    const int bh = blockIdx.y;
    const int b = bh >> 5, h = bh & 31;
    const int kvh = h >> 2;
    const int m0 = blockIdx.x * 128;
    const float* __restrict__ A  = g_scores + (size_t)bh * Ss * Ss;                // lda=Ss
    const float* __restrict__ Bv = g_v + (size_t)b * Ss * KVD + (size_t)kvh * HDd; // B[k*KVD+n]
    float* __restrict__ C = g_attn + (size_t)b * Ss * QD + (size_t)h * HDd;        // ldc=QD

    __shared__ __align__(16) float As[16][128];
    __shared__ __align__(16) float Bs[16][128];
    const int tid = threadIdx.x;
    const int ty = tid >> 4, tx = tid & 15;

    float acc[8][8];
#pragma unroll
    for (int i = 0; i < 8; i++)
#pragma unroll
        for (int j = 0; j < 8; j++) acc[i][j] = 0.f;

    const int kmax = m0 + 128;   // P rows in this tile are exactly 0 beyond m0+127
    for (int k0 = 0; k0 < kmax; k0 += 16) {
#pragma unroll
        for (int i = 0; i < 2; i++) {
            int idx = tid * 2 + i;
            int r = idx >> 2, c4 = idx & 3;
            float4 va = *(const float4*)(A + (size_t)(m0 + r) * Ss + k0 + c4 * 4);
            As[c4 * 4 + 0][r] = va.x; As[c4 * 4 + 1][r] = va.y;
            As[c4 * 4 + 2][r] = va.z; As[c4 * 4 + 3][r] = va.w;
            int kk = idx >> 5, c = idx & 31;
            float4 vb = *(const float4*)(Bv + (size_t)(k0 + kk) * KVD + c * 4);
            *(float4*)(&Bs[kk][c * 4]) = vb;
        }
        __syncthreads();
#pragma unroll
        for (int kk = 0; kk < 16; kk++) {
            float a[8], bfrag[8];
#pragma unroll
            for (int i = 0; i < 8; i++) a[i] = As[kk][ty * 8 + i];
#pragma unroll
            for (int j = 0; j < 8; j++) bfrag[j] = Bs[kk][tx * 8 + j];
#pragma unroll
            for (int i = 0; i < 8; i++)
#pragma unroll
                for (int j = 0; j < 8; j++) acc[i][j] = fmaf(a[i], bfrag[j], acc[i][j]);
        }
        __syncthreads();
    }
#pragma unroll
    for (int i = 0; i < 8; i++) {
        size_t row = (size_t)(m0 + ty * 8 + i) * QD + tx * 8;
#pragma unroll
        for (int j = 0; j < 8; j += 4) {
            float4 v = make_float4(acc[i][j], acc[i][j + 1], acc[i][j + 2], acc[i][j + 3]);
            *(float4*)(C + row + j) = v;
        }
    }
}

// ---------------- launch ----------------
extern "C" void kernel_launch(void* const* d_in, const int* in_sizes, int n_in,
                              void* d_out, int out_size)
{
    // Robust input identification by element count.
    // hidden: 8,388,608  Wq/Wo: 16,777,216 (x2)  Wk/Wv: 4,194,304 (x2)
    // mask: 2,097,152  posid: 2,048
    const float* hidden = nullptr;
    const float* big16[2] = {nullptr, nullptr};
    const float* sml4[2]  = {nullptr, nullptr};
    const int*   posid = nullptr;
    int hidden_idx = -1, nb = 0, ns = 0;
    for (int i = 0; i < n_in; i++) {
        if (in_sizes[i] == 8388608)               { hidden = (const float*)d_in[i]; hidden_idx = i; }
        else if (in_sizes[i] == 16777216 && nb<2) { big16[nb++] = (const float*)d_in[i]; }
        else if (in_sizes[i] == 4194304  && ns<2) { sml4[ns++]  = (const float*)d_in[i]; }
        else if (in_sizes[i] == 2048)             { posid = (const int*)d_in[i]; }
    }
    const float* Wq = (hidden_idx == 0) ? big16[0] : big16[1];
    const float* Wo = (hidden_idx == 0) ? big16[1] : big16[0];
    const float* Wk = sml4[0];
    const float* Wv = sml4[1];
    float* out = (float*)d_out;

    void *pq, *pk, *pv, *pattn, *pwq, *pwk, *pwv, *pwo;
    cudaGetSymbolAddress(&pq, g_q);
    cudaGetSymbolAddress(&pk, g_k);
    cudaGetSymbolAddress(&pv, g_v);
    cudaGetSymbolAddress(&pattn, g_attn);
    cudaGetSymbolAddress(&pwq, g_wq);
    cudaGetSymbolAddress(&pwk, g_wk);
    cudaGetSymbolAddress(&pwv, g_wv);
    cudaGetSymbolAddress(&pwo, g_wo);

    const size_t nQ = (size_t)QD * Hh;    // 16.7M
    const size_t nK = (size_t)KVD * Hh;   // 4.2M
    const size_t nO = (size_t)Hh * QD;    // 16.7M

    init_kernel<<<1, 32>>>();
    abssum_kernel<<<1024, 256>>>(Wq, nQ, 0);
    abssum_kernel<<<1024, 256>>>(Wk, nK, 1);
    abssum_kernel<<<1024, 256>>>(Wv, nK, 2);
    abssum_kernel<<<1024, 256>>>(Wo, nO, 3);

    quantize_kernel<<<4096, 256>>>(Wq, (int8_t*)pwq, nQ, 0);
    quantize_kernel<<<4096, 256>>>(Wk, (int8_t*)pwk, nK, 1);
    quantize_kernel<<<4096, 256>>>(Wv, (int8_t*)pwv, nK, 2);
    quantize_kernel<<<4096, 256>>>(Wo, (int8_t*)pwo, nO, 3);

    gemm_nt_ternary<<<dim3(QD / 128, MTOK / 128), 256>>>(hidden, (const int8_t*)pwq,
                                                         (float*)pq, QD, Hh, 0);
    gemm_nt_ternary<<<dim3(KVD / 128, MTOK / 128), 256>>>(hidden, (const int8_t*)pwk,
                                                          (float*)pk, KVD, Hh, 1);
    gemm_nt_ternary<<<dim3(KVD / 128, MTOK / 128), 256>>>(hidden, (const int8_t*)pwv,
                                                          (float*)pv, KVD, Hh, 2);

    rope_kernel<<<(int)(((size_t)MTOK * NHq * 64 + 255) / 256), 256>>>((float*)pq, NHq, posid);
    rope_kernel<<<(int)(((size_t)MTOK * NKVh * 64 + 255) / 256), 256>>>((float*)pk, NKVh, posid);

    scores_kernel<<<dim3(8, 8, Bb * NHq), 256>>>();
    softmax_kernel<<<Bb * NHq * Ss, 256>>>();
    pv_kernel<<<dim3(8, Bb * NHq), 256>>>();

    gemm_nt_ternary<<<dim3(Hh / 128, MTOK / 128), 256>>>((const float*)pattn,
                                                         (const int8_t*)pwo,
                                                         out, Hh, QD, 3);
}

// round 5
// speedup vs baseline: 2.2539x; 2.2539x over previous
#include <cuda_runtime.h>
#include <cuda_bf16.h>
#include <math.h>
#include <stdint.h>

// Problem constants
constexpr int Bb   = 2;
constexpr int Ss   = 1024;
constexpr int Hh   = 4096;
constexpr int NHq  = 32;
constexpr int NKVh = 8;
constexpr int HDd  = 128;
constexpr int MTOK = Bb * Ss;             // 2048
constexpr int QD   = NHq * HDd;           // 4096
constexpr int KVD  = NKVh * HDd;          // 1024
constexpr int K2   = 2 * Hh;              // 8192 (hi/lo doubled K)

// ---------------- device scratch (static; allocation-free) ----------------
__device__ float          g_q[(size_t)MTOK * QD];        // 32 MB
__device__ float          g_k[(size_t)MTOK * KVD];       // 8 MB
__device__ float          g_v[(size_t)MTOK * KVD];       // 8 MB
__device__ float          g_attn[(size_t)MTOK * QD];     // 32 MB
__device__ float          g_scores[(size_t)Bb * NHq * Ss * Ss];  // 256 MB
__device__ __nv_bfloat16  g_a2[(size_t)MTOK * K2];       // 32 MB (split activations)
__device__ __nv_bfloat16  g_w2q[(size_t)QD  * K2];       // 64 MB
__device__ __nv_bfloat16  g_w2k[(size_t)KVD * K2];       // 16 MB
__device__ __nv_bfloat16  g_w2v[(size_t)KVD * K2];       // 16 MB
__device__ __nv_bfloat16  g_w2o[(size_t)Hh  * K2];       // 64 MB
__device__ double         g_absum[4];
__device__ float          g_gamma[4];

// ---------------- gamma: abs-sum reduction ----------------
__global__ void init_kernel() {
    if (threadIdx.x < 4) g_absum[threadIdx.x] = 0.0;
}

__global__ void abssum_kernel(const float* __restrict__ w, size_t n, int idx) {
    float s = 0.f;
    for (size_t i = (size_t)blockIdx.x * blockDim.x + threadIdx.x; i < n;
         i += (size_t)gridDim.x * blockDim.x)
        s += fabsf(w[i]);
    __shared__ double sh[256];
    sh[threadIdx.x] = (double)s;
    __syncthreads();
    for (int o = 128; o > 0; o >>= 1) {
        if ((int)threadIdx.x < o) sh[threadIdx.x] += sh[threadIdx.x + o];
        __syncthreads();
    }
    if (threadIdx.x == 0) atomicAdd(&g_absum[idx], sh[0]);
}

// ---------------- ternary quantization -> duplicated bf16 [n][2k] ----------------
__global__ void quantize_dup_kernel(const float* __restrict__ w,
                                    __nv_bfloat16* __restrict__ t2,
                                    size_t n, int idx) {
    float gamma = (float)(g_absum[idx] / (double)n) + 1e-5f;
    if (blockIdx.x == 0 && threadIdx.x == 0) g_gamma[idx] = gamma;
    for (size_t i = (size_t)blockIdx.x * blockDim.x + threadIdx.x; i < n;
         i += (size_t)gridDim.x * blockDim.x) {
        float r = rintf(w[i] / gamma);
        r = fminf(1.f, fmaxf(-1.f, r));
        __nv_bfloat16 b = __float2bfloat16_rn(r);   // -1/0/1 exact in bf16
        t2[2 * i]     = b;
        t2[2 * i + 1] = b;
    }
}

// ---------------- fp32 -> (hi,lo) bf16 split, interleaved [m][2k] ----------------
__global__ void split_kernel(const float* __restrict__ x,
                             __nv_bfloat16* __restrict__ a2, size_t n) {
    for (size_t i = (size_t)blockIdx.x * blockDim.x + threadIdx.x; i < n;
         i += (size_t)gridDim.x * blockDim.x) {
        float f = x[i];
        __nv_bfloat16 hi = __float2bfloat16_rn(f);
        __nv_bfloat16 lo = __float2bfloat16_rn(f - __bfloat162float(hi));
        a2[2 * i]     = hi;
        a2[2 * i + 1] = lo;
    }
}

// ---------------- bf16 tensor-core GEMM: C = gamma * A2[M,K2] . W2[N,K2]^T ----------------
__device__ __forceinline__ void mma16816(float* c, const uint32_t* a, const uint32_t* b) {
    asm volatile(
        "mma.sync.aligned.m16n8k16.row.col.f32.bf16.bf16.f32 "
        "{%0,%1,%2,%3}, {%4,%5,%6,%7}, {%8,%9}, {%0,%1,%2,%3};"
        : "+f"(c[0]), "+f"(c[1]), "+f"(c[2]), "+f"(c[3])
        : "r"(a[0]), "r"(a[1]), "r"(a[2]), "r"(a[3]), "r"(b[0]), "r"(b[1]));
}

constexpr int SSTRIDE = 72;   // bf16 elems per smem row (144B, 16B-aligned, conflict-free frags)

__global__ __launch_bounds__(256) void gemm_mma(
    const __nv_bfloat16* __restrict__ A,   // [M, K2] row-major
    const __nv_bfloat16* __restrict__ Bw,  // [N, K2] row-major (k-contiguous)
    float* __restrict__ C, int N, int gidx)
{
    __shared__ __align__(16) __nv_bfloat16 As[128 * SSTRIDE];
    __shared__ __align__(16) __nv_bfloat16 Bs[128 * SSTRIDE];

    const int tid  = threadIdx.x;
    const int wid  = tid >> 5;
    const int lane = tid & 31;
    const int g    = lane >> 2;          // group id 0..7
    const int t    = lane & 3;           // thread-in-group 0..3
    const int m0   = blockIdx.y * 128;
    const int n0   = blockIdx.x * 128;
    const int wrow = (wid >> 2) * 64;    // warp M offset within block (2 rows of warps)
    const int wcol = (wid & 3) * 32;     // warp N offset within block (4 cols of warps)

    float acc[4][4][4];
#pragma unroll
    for (int i = 0; i < 4; i++)
#pragma unroll
        for (int j = 0; j < 4; j++)
#pragma unroll
            for (int r = 0; r < 4; r++) acc[i][j][r] = 0.f;

    for (int kc = 0; kc < K2; kc += 64) {
        // ---- load 128x64 bf16 tiles of A and B (16B per thread per tile per step) ----
#pragma unroll
        for (int l = 0; l < 4; l++) {
            int seg = tid + l * 256;               // 0..1023
            int row = seg >> 3;
            int cs  = (seg & 7) * 8;
            *(uint4*)&As[row * SSTRIDE + cs] =
                *(const uint4*)&A[(size_t)(m0 + row) * K2 + kc + cs];
            *(uint4*)&Bs[row * SSTRIDE + cs] =
                *(const uint4*)&Bw[(size_t)(n0 + row) * K2 + kc + cs];
        }
        __syncthreads();

#pragma unroll
        for (int kk = 0; kk < 64; kk += 16) {
            uint32_t afr[4][4], bfr[4][2];
#pragma unroll
            for (int mt = 0; mt < 4; mt++) {
                int m = wrow + mt * 16 + g;
                afr[mt][0] = *(const uint32_t*)&As[(m    ) * SSTRIDE + kk + 2 * t    ];
                afr[mt][1] = *(const uint32_t*)&As[(m + 8) * SSTRIDE + kk + 2 * t    ];
                afr[mt][2] = *(const uint32_t*)&As[(m    ) * SSTRIDE + kk + 2 * t + 8];
                afr[mt][3] = *(const uint32_t*)&As[(m + 8) * SSTRIDE + kk + 2 * t + 8];
            }
#pragma unroll
            for (int nt = 0; nt < 4; nt++) {
                int n = wcol + nt * 8 + g;
                bfr[nt][0] = *(const uint32_t*)&Bs[n * SSTRIDE + kk + 2 * t    ];
                bfr[nt][1] = *(const uint32_t*)&Bs[n * SSTRIDE + kk + 2 * t + 8];
            }
#pragma unroll
            for (int mt = 0; mt < 4; mt++)
#pragma unroll
                for (int nt = 0; nt < 4; nt++)
                    mma16816(acc[mt][nt], afr[mt], bfr[nt]);
        }
        __syncthreads();
    }

    const float gamma = g_gamma[gidx];
#pragma unroll
    for (int mt = 0; mt < 4; mt++) {
#pragma unroll
        for (int nt = 0; nt < 4; nt++) {
            int m = m0 + wrow + mt * 16 + g;
            int n = n0 + wcol + nt * 8 + 2 * t;
            float2 lo = make_float2(acc[mt][nt][0] * gamma, acc[mt][nt][1] * gamma);
            float2 hi = make_float2(acc[mt][nt][2] * gamma, acc[mt][nt][3] * gamma);
            *(float2*)&C[(size_t)m * N + n]       = lo;
            *(float2*)&C[(size_t)(m + 8) * N + n] = hi;
        }
    }
}

// ---------------- RoPE (in place), uses position_ids ----------------
__global__ void rope_kernel(float* __restrict__ x, int nheads,
                            const int* __restrict__ pos_ids) {
    size_t idx = (size_t)blockIdx.x * blockDim.x + threadIdx.x;
    size_t total = (size_t)MTOK * nheads * 64;
    if (idx >= total) return;
    int d = (int)(idx & 63);
    size_t th = idx >> 6;
    int head = (int)(th % nheads);
    size_t tok = th / nheads;
    int pos = pos_ids[tok];
    float inv_freq = 1.0f / powf(10000.0f, (float)d * (1.0f / 64.0f));
    float fr = (float)pos * inv_freq;
    float s, c;
    sincosf(fr, &s, &c);
    float* base = x + tok * ((size_t)nheads * HDd) + (size_t)head * HDd;
    float x1 = base[d], x2 = base[d + 64];
    base[d]      = x1 * c - x2 * s;
    base[d + 64] = x2 * c + x1 * s;
}

// ---------------- scores: S[bh,m,n] = (q.k)/sqrt(HD), causal lower-tri only ----------------
__global__ __launch_bounds__(256) void scores_kernel() {
    const int bh = blockIdx.z;
    const int b = bh >> 5, h = bh & 31;
    const int kvh = h >> 2;
    const int m0 = blockIdx.y * 128;
    const int n0 = blockIdx.x * 128;
    if (n0 > m0) return;

    const float* __restrict__ A  = g_q + (size_t)b * Ss * QD  + (size_t)h * HDd;
    const float* __restrict__ Bk = g_k + (size_t)b * Ss * KVD + (size_t)kvh * HDd;
    float* __restrict__ C = g_scores + (size_t)bh * Ss * Ss;

    __shared__ __align__(16) float As[16][128];
    __shared__ __align__(16) float Bs[16][128];
    const int tid = threadIdx.x;
    const int ty = tid >> 4, tx = tid & 15;

    float acc[8][8];
#pragma unroll
    for (int i = 0; i < 8; i++)
#pragma unroll
        for (int j = 0; j < 8; j++) acc[i][j] = 0.f;

    for (int k0 = 0; k0 < HDd; k0 += 16) {
#pragma unroll
        for (int i = 0; i < 2; i++) {
            int idx = tid * 2 + i;
            int r = idx >> 2, c4 = idx & 3;
            float4 va = *(const float4*)(A + (size_t)(m0 + r) * QD + k0 + c4 * 4);
            As[c4 * 4 + 0][r] = va.x; As[c4 * 4 + 1][r] = va.y;
            As[c4 * 4 + 2][r] = va.z; As[c4 * 4 + 3][r] = va.w;
            float4 vb = *(const float4*)(Bk + (size_t)(n0 + r) * KVD + k0 + c4 * 4);
            Bs[c4 * 4 + 0][r] = vb.x; Bs[c4 * 4 + 1][r] = vb.y;
            Bs[c4 * 4 + 2][r] = vb.z; Bs[c4 * 4 + 3][r] = vb.w;
        }
        __syncthreads();
#pragma unroll
        for (int kk = 0; kk < 16; kk++) {
            float a[8], bfrag[8];
#pragma unroll
            for (int i = 0; i < 8; i++) a[i] = As[kk][ty * 8 + i];
#pragma unroll
            for (int j = 0; j < 8; j++) bfrag[j] = Bs[kk][tx * 8 + j];
#pragma unroll
            for (int i = 0; i < 8; i++)
#pragma unroll
                for (int j = 0; j < 8; j++) acc[i][j] = fmaf(a[i], bfrag[j], acc[i][j]);
        }
        __syncthreads();
    }
    const float scale = 0.08838834764831845f;
#pragma unroll
    for (int i = 0; i < 8; i++) {
        int m = m0 + ty * 8 + i;
#pragma unroll
        for (int j = 0; j < 8; j++) {
            int n = n0 + tx * 8 + j;
            if (n <= m) C[(size_t)m * Ss + n] = acc[i][j] * scale;
        }
    }
}

// ---------------- row softmax over j<=i, zero-fill j>i ----------------
__global__ void softmax_kernel() {
    const int row = blockIdx.x;
    const int i = row & (Ss - 1);
    float* __restrict__ p = g_scores + (size_t)row * Ss;
    __shared__ float buf[Ss];
    __shared__ float red[40];
    const int len = i + 1;

    float mx = -INFINITY;
    for (int j = threadIdx.x; j < len; j += blockDim.x) {
        float v = p[j]; buf[j] = v; mx = fmaxf(mx, v);
    }
#pragma unroll
    for (int o = 16; o; o >>= 1) mx = fmaxf(mx, __shfl_xor_sync(0xffffffffu, mx, o));
    if ((threadIdx.x & 31) == 0) red[threadIdx.x >> 5] = mx;
    __syncthreads();
    if (threadIdx.x == 0) {
        float m = red[0];
        for (int w = 1; w < 8; w++) m = fmaxf(m, red[w]);
        red[32] = m;
    }
    __syncthreads();
    mx = red[32];

    float sum = 0.f;
    for (int j = threadIdx.x; j < len; j += blockDim.x) {
        float e = expf(buf[j] - mx); buf[j] = e; sum += e;
    }
#pragma unroll
    for (int o = 16; o; o >>= 1) sum += __shfl_xor_sync(0xffffffffu, sum, o);
    __syncthreads();
    if ((threadIdx.x & 31) == 0) red[threadIdx.x >> 5] = sum;
    __syncthreads();
    if (threadIdx.x == 0) {
        float s = red[0];
        for (int w = 1; w < 8; w++) s += red[w];
        red[33] = s;
    }
    __syncthreads();
    const float inv = 1.f / red[33];
    for (int j = threadIdx.x; j < Ss; j += blockDim.x)
        p[j] = (j < len) ? buf[j] * inv : 0.f;
}

// ---------------- PV: attn = P @ V (NN GEMM, causal K-limit) ----------------
__global__ __launch_bounds__(256) void pv_kernel() {
    const int bh = blockIdx.y;
    const int b = bh >> 5, h = bh & 31;
    const int kvh = h >> 2;
    const int m0 = blockIdx.x * 128;
    const float* __restrict__ A  = g_scores + (size_t)bh * Ss * Ss;
    const float* __restrict__ Bv = g_v + (size_t)b * Ss * KVD + (size_t)kvh * HDd;
    float* __restrict__ C = g_attn + (size_t)b * Ss * QD + (size_t)h * HDd;

    __shared__ __align__(16) float As[16][128];
    __shared__ __align__(16) float Bs[16][128];
    const int tid = threadIdx.x;
    const int ty = tid >> 4, tx = tid & 15;

    float acc[8][8];
#pragma unroll
    for (int i = 0; i < 8; i++)
#pragma unroll
        for (int j = 0; j < 8; j++) acc[i][j] = 0.f;

    const int kmax = m0 + 128;
    for (int k0 = 0; k0 < kmax; k0 += 16) {
#pragma unroll
        for (int i = 0; i < 2; i++) {
            int idx = tid * 2 + i;
            int r = idx >> 2, c4 = idx & 3;
            float4 va = *(const float4*)(A + (size_t)(m0 + r) * Ss + k0 + c4 * 4);
            As[c4 * 4 + 0][r] = va.x; As[c4 * 4 + 1][r] = va.y;
            As[c4 * 4 + 2][r] = va.z; As[c4 * 4 + 3][r] = va.w;
            int kk = idx >> 5, c = idx & 31;
            float4 vb = *(const float4*)(Bv + (size_t)(k0 + kk) * KVD + c * 4);
            *(float4*)(&Bs[kk][c * 4]) = vb;
        }
        __syncthreads();
#pragma unroll
        for (int kk = 0; kk < 16; kk++) {
            float a[8], bfrag[8];
#pragma unroll
            for (int i = 0; i < 8; i++) a[i] = As[kk][ty * 8 + i];
#pragma unroll
            for (int j = 0; j < 8; j++) bfrag[j] = Bs[kk][tx * 8 + j];
#pragma unroll
            for (int i = 0; i < 8; i++)
#pragma unroll
                for (int j = 0; j < 8; j++) acc[i][j] = fmaf(a[i], bfrag[j], acc[i][j]);
        }
        __syncthreads();
    }
#pragma unroll
    for (int i = 0; i < 8; i++) {
        size_t row = (size_t)(m0 + ty * 8 + i) * QD + tx * 8;
#pragma unroll
        for (int j = 0; j < 8; j += 4) {
            float4 v = make_float4(acc[i][j], acc[i][j + 1], acc[i][j + 2], acc[i][j + 3]);
            *(float4*)(C + row + j) = v;
        }
    }
}

// ---------------- launch ----------------
extern "C" void kernel_launch(void* const* d_in, const int* in_sizes, int n_in,
                              void* d_out, int out_size)
{
    const float* hidden = nullptr;
    const float* big16[2] = {nullptr, nullptr};
    const float* sml4[2]  = {nullptr, nullptr};
    const int*   posid = nullptr;
    int hidden_idx = -1, nb = 0, ns = 0;
    for (int i = 0; i < n_in; i++) {
        if (in_sizes[i] == 8388608)               { hidden = (const float*)d_in[i]; hidden_idx = i; }
        else if (in_sizes[i] == 16777216 && nb<2) { big16[nb++] = (const float*)d_in[i]; }
        else if (in_sizes[i] == 4194304  && ns<2) { sml4[ns++]  = (const float*)d_in[i]; }
        else if (in_sizes[i] == 2048)             { posid = (const int*)d_in[i]; }
    }
    const float* Wq = (hidden_idx == 0) ? big16[0] : big16[1];
    const float* Wo = (hidden_idx == 0) ? big16[1] : big16[0];
    const float* Wk = sml4[0];
    const float* Wv = sml4[1];
    float* out = (float*)d_out;

    void *pq, *pk, *pv, *pattn, *pa2, *pw2q, *pw2k, *pw2v, *pw2o;
    cudaGetSymbolAddress(&pq, g_q);
    cudaGetSymbolAddress(&pk, g_k);
    cudaGetSymbolAddress(&pv, g_v);
    cudaGetSymbolAddress(&pattn, g_attn);
    cudaGetSymbolAddress(&pa2, g_a2);
    cudaGetSymbolAddress(&pw2q, g_w2q);
    cudaGetSymbolAddress(&pw2k, g_w2k);
    cudaGetSymbolAddress(&pw2v, g_w2v);
    cudaGetSymbolAddress(&pw2o, g_w2o);

    const size_t nQ = (size_t)QD * Hh;    // 16.7M
    const size_t nK = (size_t)KVD * Hh;   // 4.2M
    const size_t nO = (size_t)Hh * QD;    // 16.7M
    const size_t nH = (size_t)MTOK * Hh;  // 8.4M

    init_kernel<<<1, 32>>>();
    abssum_kernel<<<1024, 256>>>(Wq, nQ, 0);
    abssum_kernel<<<1024, 256>>>(Wk, nK, 1);
    abssum_kernel<<<1024, 256>>>(Wv, nK, 2);
    abssum_kernel<<<1024, 256>>>(Wo, nO, 3);

    quantize_dup_kernel<<<4096, 256>>>(Wq, (__nv_bfloat16*)pw2q, nQ, 0);
    quantize_dup_kernel<<<4096, 256>>>(Wk, (__nv_bfloat16*)pw2k, nK, 1);
    quantize_dup_kernel<<<4096, 256>>>(Wv, (__nv_bfloat16*)pw2v, nK, 2);
    quantize_dup_kernel<<<4096, 256>>>(Wo, (__nv_bfloat16*)pw2o, nO, 3);

    // hidden -> split bf16 (hi/lo interleaved along K)
    split_kernel<<<4096, 256>>>(hidden, (__nv_bfloat16*)pa2, nH);

    // projections on tensor cores
    gemm_mma<<<dim3(QD / 128, MTOK / 128), 256>>>((const __nv_bfloat16*)pa2,
                                                  (const __nv_bfloat16*)pw2q,
                                                  (float*)pq, QD, 0);
    gemm_mma<<<dim3(KVD / 128, MTOK / 128), 256>>>((const __nv_bfloat16*)pa2,
                                                   (const __nv_bfloat16*)pw2k,
                                                   (float*)pk, KVD, 1);
    gemm_mma<<<dim3(KVD / 128, MTOK / 128), 256>>>((const __nv_bfloat16*)pa2,
                                                   (const __nv_bfloat16*)pw2v,
                                                   (float*)pv, KVD, 2);

    rope_kernel<<<(int)(((size_t)MTOK * NHq * 64 + 255) / 256), 256>>>((float*)pq, NHq, posid);
    rope_kernel<<<(int)(((size_t)MTOK * NKVh * 64 + 255) / 256), 256>>>((float*)pk, NKVh, posid);

    scores_kernel<<<dim3(8, 8, Bb * NHq), 256>>>();
    softmax_kernel<<<Bb * NHq * Ss, 256>>>();
    pv_kernel<<<dim3(8, Bb * NHq), 256>>>();

    // attn -> split bf16, then output projection on tensor cores
    split_kernel<<<4096, 256>>>((const float*)pattn, (__nv_bfloat16*)pa2, nH);
    gemm_mma<<<dim3(Hh / 128, MTOK / 128), 256>>>((const __nv_bfloat16*)pa2,
                                                  (const __nv_bfloat16*)pw2o,
                                                  out, Hh, 3);
}

// round 6
// speedup vs baseline: 2.5139x; 1.1153x over previous
#include <cuda_runtime.h>
#include <cuda_bf16.h>
#include <math.h>
#include <stdint.h>

// Problem constants
constexpr int Bb   = 2;
constexpr int Ss   = 1024;
constexpr int Hh   = 4096;
constexpr int NHq  = 32;
constexpr int NKVh = 8;
constexpr int HDd  = 128;
constexpr int MTOK = Bb * Ss;             // 2048
constexpr int QD   = NHq * HDd;           // 4096
constexpr int KVD  = NKVh * HDd;          // 1024

// ---------------- device scratch (static; allocation-free) ----------------
__device__ float          g_q[(size_t)MTOK * QD];        // 32 MB
__device__ float          g_k[(size_t)MTOK * KVD];       // 8 MB
__device__ float          g_v[(size_t)MTOK * KVD];       // 8 MB
__device__ float          g_attn[(size_t)MTOK * QD];     // 32 MB
__device__ float          g_scores[(size_t)Bb * NHq * Ss * Ss];  // 256 MB
__device__ __nv_bfloat16  g_ahi[(size_t)MTOK * Hh];      // 16 MB (activation hi)
__device__ __nv_bfloat16  g_alo[(size_t)MTOK * Hh];      // 16 MB (activation lo)
__device__ __nv_bfloat16  g_wq[(size_t)QD  * Hh];        // 32 MB
__device__ __nv_bfloat16  g_wk[(size_t)KVD * Hh];        // 8 MB
__device__ __nv_bfloat16  g_wv[(size_t)KVD * Hh];        // 8 MB
__device__ __nv_bfloat16  g_wo[(size_t)Hh  * QD];        // 32 MB
__device__ __nv_bfloat16  g_vhi[(size_t)Bb * NKVh * HDd * Ss];  // 4 MB (V^T hi)
__device__ __nv_bfloat16  g_vlo[(size_t)Bb * NKVh * HDd * Ss];  // 4 MB (V^T lo)
__device__ double         g_absum[4];
__device__ float          g_gamma[4];

// ---------------- helpers ----------------
__device__ __forceinline__ uint32_t packbf(float a, float b) {
    __nv_bfloat162 t = __floats2bfloat162_rn(a, b);   // a -> low, b -> high
    return *(uint32_t*)&t;
}

__device__ __forceinline__ void mma16816(float* c, const uint32_t* a, const uint32_t* b) {
    asm volatile(
        "mma.sync.aligned.m16n8k16.row.col.f32.bf16.bf16.f32 "
        "{%0,%1,%2,%3}, {%4,%5,%6,%7}, {%8,%9}, {%0,%1,%2,%3};"
        : "+f"(c[0]), "+f"(c[1]), "+f"(c[2]), "+f"(c[3])
        : "r"(a[0]), "r"(a[1]), "r"(a[2]), "r"(a[3]), "r"(b[0]), "r"(b[1]));
}

constexpr int ST = 40;   // smem row stride in bf16 (80B: conflict-free frag loads)

// ---------------- gamma: abs-sum reduction ----------------
__global__ void init_kernel() {
    if (threadIdx.x < 4) g_absum[threadIdx.x] = 0.0;
}

__global__ void abssum_kernel(const float* __restrict__ w, size_t n, int idx) {
    float s = 0.f;
    for (size_t i = (size_t)blockIdx.x * blockDim.x + threadIdx.x; i < n;
         i += (size_t)gridDim.x * blockDim.x)
        s += fabsf(w[i]);
    __shared__ double sh[256];
    sh[threadIdx.x] = (double)s;
    __syncthreads();
    for (int o = 128; o > 0; o >>= 1) {
        if ((int)threadIdx.x < o) sh[threadIdx.x] += sh[threadIdx.x + o];
        __syncthreads();
    }
    if (threadIdx.x == 0) atomicAdd(&g_absum[idx], sh[0]);
}

// ---------------- ternary quantization -> single bf16 plane ----------------
__global__ void quantize_kernel(const float* __restrict__ w,
                                __nv_bfloat16* __restrict__ t, size_t n, int idx) {
    float gamma = (float)(g_absum[idx] / (double)n) + 1e-5f;
    if (blockIdx.x == 0 && threadIdx.x == 0) g_gamma[idx] = gamma;
    for (size_t i = (size_t)blockIdx.x * blockDim.x + threadIdx.x; i < n;
         i += (size_t)gridDim.x * blockDim.x) {
        float r = rintf(w[i] / gamma);
        r = fminf(1.f, fmaxf(-1.f, r));
        t[i] = __float2bfloat16_rn(r);
    }
}

// ---------------- fp32 -> (hi,lo) bf16 planes ----------------
__global__ void split2_kernel(const float* __restrict__ x,
                              __nv_bfloat16* __restrict__ hi,
                              __nv_bfloat16* __restrict__ lo, size_t n) {
    for (size_t i = (size_t)blockIdx.x * blockDim.x + threadIdx.x; i < n;
         i += (size_t)gridDim.x * blockDim.x) {
        float f = x[i];
        __nv_bfloat16 h = __float2bfloat16_rn(f);
        hi[i] = h;
        lo[i] = __float2bfloat16_rn(f - __bfloat162float(h));
    }
}

// ---------------- V -> transposed hi/lo planes: vt[bk][d][s] ----------------
__global__ void vsplit_kernel() {
    size_t idx = (size_t)blockIdx.x * blockDim.x + threadIdx.x;
    if (idx >= (size_t)Bb * NKVh * HDd * Ss) return;
    int s  = (int)(idx & (Ss - 1));
    int d  = (int)((idx >> 10) & 127);
    int bk = (int)(idx >> 17);
    int b  = bk >> 3, kv = bk & 7;
    float v = g_v[((size_t)(b * Ss + s)) * KVD + kv * HDd + d];
    __nv_bfloat16 h = __float2bfloat16_rn(v);
    g_vhi[idx] = h;
    g_vlo[idx] = __float2bfloat16_rn(v - __bfloat162float(h));
}

// ---------------- projection GEMM: C = gamma*(Ahi+Alo)[M,K] . W[N,K]^T ----------------
__global__ __launch_bounds__(256) void gemm_mma2(
    const __nv_bfloat16* __restrict__ Ahi, const __nv_bfloat16* __restrict__ Alo,
    const __nv_bfloat16* __restrict__ W, float* __restrict__ C,
    int N, int K, int gidx)
{
    __shared__ __align__(16) __nv_bfloat16 sah[128 * ST];
    __shared__ __align__(16) __nv_bfloat16 sal[128 * ST];
    __shared__ __align__(16) __nv_bfloat16 sb [128 * ST];

    const int tid  = threadIdx.x;
    const int wid  = tid >> 5;
    const int lane = tid & 31;
    const int g    = lane >> 2;
    const int t    = lane & 3;
    const int m0   = blockIdx.y * 128;
    const int n0   = blockIdx.x * 128;
    const int wrow = (wid >> 2) * 64;
    const int wcol = (wid & 3) * 32;

    float acc[4][4][4];
#pragma unroll
    for (int i = 0; i < 4; i++)
#pragma unroll
        for (int j = 0; j < 4; j++)
#pragma unroll
            for (int r = 0; r < 4; r++) acc[i][j][r] = 0.f;

    for (int kc = 0; kc < K; kc += 32) {
#pragma unroll
        for (int l = 0; l < 2; l++) {
            int seg = tid + l * 256;        // 0..511
            int row = seg >> 2;
            int cs  = (seg & 3) * 8;
            *(uint4*)&sah[row * ST + cs] = *(const uint4*)&Ahi[(size_t)(m0 + row) * K + kc + cs];
            *(uint4*)&sal[row * ST + cs] = *(const uint4*)&Alo[(size_t)(m0 + row) * K + kc + cs];
            *(uint4*)&sb [row * ST + cs] = *(const uint4*)&W  [(size_t)(n0 + row) * K + kc + cs];
        }
        __syncthreads();

#pragma unroll
        for (int kk = 0; kk < 32; kk += 16) {
            uint32_t ah[4][4], al[4][4], bf[4][2];
#pragma unroll
            for (int mt = 0; mt < 4; mt++) {
                int m = wrow + mt * 16 + g;
                ah[mt][0] = *(const uint32_t*)&sah[(m    ) * ST + kk + 2 * t    ];
                ah[mt][1] = *(const uint32_t*)&sah[(m + 8) * ST + kk + 2 * t    ];
                ah[mt][2] = *(const uint32_t*)&sah[(m    ) * ST + kk + 2 * t + 8];
                ah[mt][3] = *(const uint32_t*)&sah[(m + 8) * ST + kk + 2 * t + 8];
                al[mt][0] = *(const uint32_t*)&sal[(m    ) * ST + kk + 2 * t    ];
                al[mt][1] = *(const uint32_t*)&sal[(m + 8) * ST + kk + 2 * t    ];
                al[mt][2] = *(const uint32_t*)&sal[(m    ) * ST + kk + 2 * t + 8];
                al[mt][3] = *(const uint32_t*)&sal[(m + 8) * ST + kk + 2 * t + 8];
            }
#pragma unroll
            for (int nt = 0; nt < 4; nt++) {
                int n = wcol + nt * 8 + g;
                bf[nt][0] = *(const uint32_t*)&sb[n * ST + kk + 2 * t    ];
                bf[nt][1] = *(const uint32_t*)&sb[n * ST + kk + 2 * t + 8];
            }
#pragma unroll
            for (int mt = 0; mt < 4; mt++)
#pragma unroll
                for (int nt = 0; nt < 4; nt++) {
                    mma16816(acc[mt][nt], ah[mt], bf[nt]);
                    mma16816(acc[mt][nt], al[mt], bf[nt]);
                }
        }
        __syncthreads();
    }

    const float gamma = g_gamma[gidx];
#pragma unroll
    for (int mt = 0; mt < 4; mt++) {
#pragma unroll
        for (int nt = 0; nt < 4; nt++) {
            int m = m0 + wrow + mt * 16 + g;
            int n = n0 + wcol + nt * 8 + 2 * t;
            float2 lo = make_float2(acc[mt][nt][0] * gamma, acc[mt][nt][1] * gamma);
            float2 hi = make_float2(acc[mt][nt][2] * gamma, acc[mt][nt][3] * gamma);
            *(float2*)&C[(size_t)m * N + n]       = lo;
            *(float2*)&C[(size_t)(m + 8) * N + n] = hi;
        }
    }
}

// ---------------- RoPE (in place), uses position_ids ----------------
__global__ void rope_kernel(float* __restrict__ x, int nheads,
                            const int* __restrict__ pos_ids) {
    size_t idx = (size_t)blockIdx.x * blockDim.x + threadIdx.x;
    size_t total = (size_t)MTOK * nheads * 64;
    if (idx >= total) return;
    int d = (int)(idx & 63);
    size_t th = idx >> 6;
    int head = (int)(th % nheads);
    size_t tok = th / nheads;
    int pos = pos_ids[tok];
    float inv_freq = 1.0f / powf(10000.0f, (float)d * (1.0f / 64.0f));
    float fr = (float)pos * inv_freq;
    float s, c;
    sincosf(fr, &s, &c);
    float* base = x + tok * ((size_t)nheads * HDd) + (size_t)head * HDd;
    float x1 = base[d], x2 = base[d + 64];
    base[d]      = x1 * c - x2 * s;
    base[d + 64] = x2 * c + x1 * s;
}

// ---------------- scores via MMA: S = (q.k)/sqrt(HD), lower-tri tiles ----------------
__global__ __launch_bounds__(256) void scores_mma() {
    const int bh = blockIdx.z;
    const int b = bh >> 5, h = bh & 31;
    const int kvh = h >> 2;
    const int m0 = blockIdx.y * 128;
    const int n0 = blockIdx.x * 128;
    if (n0 > m0) return;

    const float* __restrict__ A  = g_q + (size_t)b * Ss * QD  + (size_t)h * HDd;
    const float* __restrict__ Bk = g_k + (size_t)b * Ss * KVD + (size_t)kvh * HDd;
    float* __restrict__ C = g_scores + (size_t)bh * Ss * Ss;

    __shared__ __align__(16) __nv_bfloat16 sqh[128 * ST];
    __shared__ __align__(16) __nv_bfloat16 sql[128 * ST];
    __shared__ __align__(16) __nv_bfloat16 skh[128 * ST];
    __shared__ __align__(16) __nv_bfloat16 skl[128 * ST];

    const int tid  = threadIdx.x;
    const int wid  = tid >> 5;
    const int lane = tid & 31;
    const int g    = lane >> 2;
    const int t    = lane & 3;
    const int wrow = (wid >> 2) * 64;
    const int wcol = (wid & 3) * 32;

    float acc[4][4][4];
#pragma unroll
    for (int i = 0; i < 4; i++)
#pragma unroll
        for (int j = 0; j < 4; j++)
#pragma unroll
            for (int r = 0; r < 4; r++) acc[i][j][r] = 0.f;

    for (int kc = 0; kc < HDd; kc += 32) {
#pragma unroll
        for (int l = 0; l < 4; l++) {
            int seg = tid + l * 256;        // 0..1023
            int row = seg >> 3;
            int c4  = (seg & 7) * 4;
            float4 va = *(const float4*)&A[(size_t)(m0 + row) * QD + kc + c4];
            float hx = __bfloat162float(__float2bfloat16_rn(va.x));
            float hy = __bfloat162float(__float2bfloat16_rn(va.y));
            float hz = __bfloat162float(__float2bfloat16_rn(va.z));
            float hw = __bfloat162float(__float2bfloat16_rn(va.w));
            *(uint32_t*)&sqh[row * ST + c4]     = packbf(hx, hy);
            *(uint32_t*)&sqh[row * ST + c4 + 2] = packbf(hz, hw);
            *(uint32_t*)&sql[row * ST + c4]     = packbf(va.x - hx, va.y - hy);
            *(uint32_t*)&sql[row * ST + c4 + 2] = packbf(va.z - hz, va.w - hw);

            float4 vb = *(const float4*)&Bk[(size_t)(n0 + row) * KVD + kc + c4];
            float gx = __bfloat162float(__float2bfloat16_rn(vb.x));
            float gy = __bfloat162float(__float2bfloat16_rn(vb.y));
            float gz = __bfloat162float(__float2bfloat16_rn(vb.z));
            float gw = __bfloat162float(__float2bfloat16_rn(vb.w));
            *(uint32_t*)&skh[row * ST + c4]     = packbf(gx, gy);
            *(uint32_t*)&skh[row * ST + c4 + 2] = packbf(gz, gw);
            *(uint32_t*)&skl[row * ST + c4]     = packbf(vb.x - gx, vb.y - gy);
            *(uint32_t*)&skl[row * ST + c4 + 2] = packbf(vb.z - gz, vb.w - gw);
        }
        __syncthreads();

#pragma unroll
        for (int kk = 0; kk < 32; kk += 16) {
            uint32_t ah[4][4], al[4][4], bh2[4][2], bl2[4][2];
#pragma unroll
            for (int mt = 0; mt < 4; mt++) {
                int m = wrow + mt * 16 + g;
                ah[mt][0] = *(const uint32_t*)&sqh[(m    ) * ST + kk + 2 * t    ];
                ah[mt][1] = *(const uint32_t*)&sqh[(m + 8) * ST + kk + 2 * t    ];
                ah[mt][2] = *(const uint32_t*)&sqh[(m    ) * ST + kk + 2 * t + 8];
                ah[mt][3] = *(const uint32_t*)&sqh[(m + 8) * ST + kk + 2 * t + 8];
                al[mt][0] = *(const uint32_t*)&sql[(m    ) * ST + kk + 2 * t    ];
                al[mt][1] = *(const uint32_t*)&sql[(m + 8) * ST + kk + 2 * t    ];
                al[mt][2] = *(const uint32_t*)&sql[(m    ) * ST + kk + 2 * t + 8];
                al[mt][3] = *(const uint32_t*)&sql[(m + 8) * ST + kk + 2 * t + 8];
            }
#pragma unroll
            for (int nt = 0; nt < 4; nt++) {
                int n = wcol + nt * 8 + g;
                bh2[nt][0] = *(const uint32_t*)&skh[n * ST + kk + 2 * t    ];
                bh2[nt][1] = *(const uint32_t*)&skh[n * ST + kk + 2 * t + 8];
                bl2[nt][0] = *(const uint32_t*)&skl[n * ST + kk + 2 * t    ];
                bl2[nt][1] = *(const uint32_t*)&skl[n * ST + kk + 2 * t + 8];
            }
#pragma unroll
            for (int mt = 0; mt < 4; mt++)
#pragma unroll
                for (int nt = 0; nt < 4; nt++) {
                    mma16816(acc[mt][nt], ah[mt], bh2[nt]);
                    mma16816(acc[mt][nt], al[mt], bh2[nt]);
                    mma16816(acc[mt][nt], ah[mt], bl2[nt]);
                }
        }
        __syncthreads();
    }

    const float scale = 0.08838834764831845f;
#pragma unroll
    for (int mt = 0; mt < 4; mt++) {
#pragma unroll
        for (int nt = 0; nt < 4; nt++) {
            int m = m0 + wrow + mt * 16 + g;
            int n = n0 + wcol + nt * 8 + 2 * t;
            if (n     <= m) C[(size_t)m * Ss + n]     = acc[mt][nt][0] * scale;
            if (n + 1 <= m) C[(size_t)m * Ss + n + 1] = acc[mt][nt][1] * scale;
            int m8 = m + 8;
            if (n     <= m8) C[(size_t)m8 * Ss + n]     = acc[mt][nt][2] * scale;
            if (n + 1 <= m8) C[(size_t)m8 * Ss + n + 1] = acc[mt][nt][3] * scale;
        }
    }
}

// ---------------- row softmax over j<=i, zero-fill j>i ----------------
__global__ void softmax_kernel() {
    const int row = blockIdx.x;
    const int i = row & (Ss - 1);
    float* __restrict__ p = g_scores + (size_t)row * Ss;
    __shared__ float buf[Ss];
    __shared__ float red[40];
    const int len = i + 1;

    float mx = -INFINITY;
    for (int j = threadIdx.x; j < len; j += blockDim.x) {
        float v = p[j]; buf[j] = v; mx = fmaxf(mx, v);
    }
#pragma unroll
    for (int o = 16; o; o >>= 1) mx = fmaxf(mx, __shfl_xor_sync(0xffffffffu, mx, o));
    if ((threadIdx.x & 31) == 0) red[threadIdx.x >> 5] = mx;
    __syncthreads();
    if (threadIdx.x == 0) {
        float m = red[0];
        for (int w = 1; w < 8; w++) m = fmaxf(m, red[w]);
        red[32] = m;
    }
    __syncthreads();
    mx = red[32];

    float sum = 0.f;
    for (int j = threadIdx.x; j < len; j += blockDim.x) {
        float e = expf(buf[j] - mx); buf[j] = e; sum += e;
    }
#pragma unroll
    for (int o = 16; o; o >>= 1) sum += __shfl_xor_sync(0xffffffffu, sum, o);
    __syncthreads();
    if ((threadIdx.x & 31) == 0) red[threadIdx.x >> 5] = sum;
    __syncthreads();
    if (threadIdx.x == 0) {
        float s = red[0];
        for (int w = 1; w < 8; w++) s += red[w];
        red[33] = s;
    }
    __syncthreads();
    const float inv = 1.f / red[33];
    for (int j = threadIdx.x; j < Ss; j += blockDim.x)
        p[j] = (j < len) ? buf[j] * inv : 0.f;
}

// ---------------- PV via MMA: attn = P @ V (B = V^T planes, causal K-limit) ----------------
__global__ __launch_bounds__(256) void pv_mma() {
    const int bh = blockIdx.y;
    const int b = bh >> 5, h = bh & 31;
    const int kvh = h >> 2;
    const int bk = b * NKVh + kvh;
    const int m0 = blockIdx.x * 128;

    const float* __restrict__ A = g_scores + (size_t)bh * Ss * Ss;           // [m][k] fp32
    const __nv_bfloat16* __restrict__ Vh = g_vhi + (size_t)bk * HDd * Ss;    // [d][k]
    const __nv_bfloat16* __restrict__ Vl = g_vlo + (size_t)bk * HDd * Ss;
    float* __restrict__ C = g_attn + (size_t)b * Ss * QD + (size_t)h * HDd;  // ldc=QD

    __shared__ __align__(16) __nv_bfloat16 sph[128 * ST];
    __shared__ __align__(16) __nv_bfloat16 spl[128 * ST];
    __shared__ __align__(16) __nv_bfloat16 svh[128 * ST];
    __shared__ __align__(16) __nv_bfloat16 svl[128 * ST];

    const int tid  = threadIdx.x;
    const int wid  = tid >> 5;
    const int lane = tid & 31;
    const int g    = lane >> 2;
    const int t    = lane & 3;
    const int wrow = (wid >> 2) * 64;
    const int wcol = (wid & 3) * 32;

    float acc[4][4][4];
#pragma unroll
    for (int i = 0; i < 4; i++)
#pragma unroll
        for (int j = 0; j < 4; j++)
#pragma unroll
            for (int r = 0; r < 4; r++) acc[i][j][r] = 0.f;

    const int kmax = m0 + 128;   // P is exactly 0 beyond the diagonal tile
    for (int kc = 0; kc < kmax; kc += 32) {
        // ---- P tile: fp32 -> hi/lo split in smem ----
#pragma unroll
        for (int l = 0; l < 4; l++) {
            int seg = tid + l * 256;
            int row = seg >> 3;
            int c4  = (seg & 7) * 4;
            float4 va = *(const float4*)&A[(size_t)(m0 + row) * Ss + kc + c4];
            float hx = __bfloat162float(__float2bfloat16_rn(va.x));
            float hy = __bfloat162float(__float2bfloat16_rn(va.y));
            float hz = __bfloat162float(__float2bfloat16_rn(va.z));
            float hw = __bfloat162float(__float2bfloat16_rn(va.w));
            *(uint32_t*)&sph[row * ST + c4]     = packbf(hx, hy);
            *(uint32_t*)&sph[row * ST + c4 + 2] = packbf(hz, hw);
            *(uint32_t*)&spl[row * ST + c4]     = packbf(va.x - hx, va.y - hy);
            *(uint32_t*)&spl[row * ST + c4 + 2] = packbf(va.z - hz, va.w - hw);
        }
        // ---- V^T tiles: direct bf16 loads ----
#pragma unroll
        for (int l = 0; l < 2; l++) {
            int seg = tid + l * 256;
            int row = seg >> 2;           // d
            int cs  = (seg & 3) * 8;
            *(uint4*)&svh[row * ST + cs] = *(const uint4*)&Vh[(size_t)row * Ss + kc + cs];
            *(uint4*)&svl[row * ST + cs] = *(const uint4*)&Vl[(size_t)row * Ss + kc + cs];
        }
        __syncthreads();

#pragma unroll
        for (int kk = 0; kk < 32; kk += 16) {
            uint32_t ah[4][4], al[4][4], bh2[4][2], bl2[4][2];
#pragma unroll
            for (int mt = 0; mt < 4; mt++) {
                int m = wrow + mt * 16 + g;
                ah[mt][0] = *(const uint32_t*)&sph[(m    ) * ST + kk + 2 * t    ];
                ah[mt][1] = *(const uint32_t*)&sph[(m + 8) * ST + kk + 2 * t    ];
                ah[mt][2] = *(const uint32_t*)&sph[(m    ) * ST + kk + 2 * t + 8];
                ah[mt][3] = *(const uint32_t*)&sph[(m + 8) * ST + kk + 2 * t + 8];
                al[mt][0] = *(const uint32_t*)&spl[(m    ) * ST + kk + 2 * t    ];
                al[mt][1] = *(const uint32_t*)&spl[(m + 8) * ST + kk + 2 * t    ];
                al[mt][2] = *(const uint32_t*)&spl[(m    ) * ST + kk + 2 * t + 8];
                al[mt][3] = *(const uint32_t*)&spl[(m + 8) * ST + kk + 2 * t + 8];
            }
#pragma unroll
            for (int nt = 0; nt < 4; nt++) {
                int n = wcol + nt * 8 + g;
                bh2[nt][0] = *(const uint32_t*)&svh[n * ST + kk + 2 * t    ];
                bh2[nt][1] = *(const uint32_t*)&svh[n * ST + kk + 2 * t + 8];
                bl2[nt][0] = *(const uint32_t*)&svl[n * ST + kk + 2 * t    ];
                bl2[nt][1] = *(const uint32_t*)&svl[n * ST + kk + 2 * t + 8];
            }
#pragma unroll
            for (int mt = 0; mt < 4; mt++)
#pragma unroll
                for (int nt = 0; nt < 4; nt++) {
                    mma16816(acc[mt][nt], ah[mt], bh2[nt]);
                    mma16816(acc[mt][nt], al[mt], bh2[nt]);
                    mma16816(acc[mt][nt], ah[mt], bl2[nt]);
                }
        }
        __syncthreads();
    }

#pragma unroll
    for (int mt = 0; mt < 4; mt++) {
#pragma unroll
        for (int nt = 0; nt < 4; nt++) {
            int m = m0 + wrow + mt * 16 + g;
            int n = wcol + nt * 8 + 2 * t;
            float2 lo = make_float2(acc[mt][nt][0], acc[mt][nt][1]);
            float2 hi = make_float2(acc[mt][nt][2], acc[mt][nt][3]);
            *(float2*)&C[(size_t)m * QD + n]       = lo;
            *(float2*)&C[(size_t)(m + 8) * QD + n] = hi;
        }
    }
}

// ---------------- launch ----------------
extern "C" void kernel_launch(void* const* d_in, const int* in_sizes, int n_in,
                              void* d_out, int out_size)
{
    const float* hidden = nullptr;
    const float* big16[2] = {nullptr, nullptr};
    const float* sml4[2]  = {nullptr, nullptr};
    const int*   posid = nullptr;
    int hidden_idx = -1, nb = 0, ns = 0;
    for (int i = 0; i < n_in; i++) {
        if (in_sizes[i] == 8388608)               { hidden = (const float*)d_in[i]; hidden_idx = i; }
        else if (in_sizes[i] == 16777216 && nb<2) { big16[nb++] = (const float*)d_in[i]; }
        else if (in_sizes[i] == 4194304  && ns<2) { sml4[ns++]  = (const float*)d_in[i]; }
        else if (in_sizes[i] == 2048)             { posid = (const int*)d_in[i]; }
    }
    const float* Wq = (hidden_idx == 0) ? big16[0] : big16[1];
    const float* Wo = (hidden_idx == 0) ? big16[1] : big16[0];
    const float* Wk = sml4[0];
    const float* Wv = sml4[1];
    float* out = (float*)d_out;

    void *pq, *pk, *pv, *pattn, *pahi, *palo, *pwq, *pwk, *pwv, *pwo;
    cudaGetSymbolAddress(&pq, g_q);
    cudaGetSymbolAddress(&pk, g_k);
    cudaGetSymbolAddress(&pv, g_v);
    cudaGetSymbolAddress(&pattn, g_attn);
    cudaGetSymbolAddress(&pahi, g_ahi);
    cudaGetSymbolAddress(&palo, g_alo);
    cudaGetSymbolAddress(&pwq, g_wq);
    cudaGetSymbolAddress(&pwk, g_wk);
    cudaGetSymbolAddress(&pwv, g_wv);
    cudaGetSymbolAddress(&pwo, g_wo);

    const size_t nQ = (size_t)QD * Hh;
    const size_t nK = (size_t)KVD * Hh;
    const size_t nO = (size_t)Hh * QD;
    const size_t nH = (size_t)MTOK * Hh;

    init_kernel<<<1, 32>>>();
    abssum_kernel<<<1024, 256>>>(Wq, nQ, 0);
    abssum_kernel<<<1024, 256>>>(Wk, nK, 1);
    abssum_kernel<<<1024, 256>>>(Wv, nK, 2);
    abssum_kernel<<<1024, 256>>>(Wo, nO, 3);

    quantize_kernel<<<4096, 256>>>(Wq, (__nv_bfloat16*)pwq, nQ, 0);
    quantize_kernel<<<4096, 256>>>(Wk, (__nv_bfloat16*)pwk, nK, 1);
    quantize_kernel<<<4096, 256>>>(Wv, (__nv_bfloat16*)pwv, nK, 2);
    quantize_kernel<<<4096, 256>>>(Wo, (__nv_bfloat16*)pwo, nO, 3);

    split2_kernel<<<4096, 256>>>(hidden, (__nv_bfloat16*)pahi, (__nv_bfloat16*)palo, nH);

    gemm_mma2<<<dim3(QD / 128, MTOK / 128), 256>>>((const __nv_bfloat16*)pahi,
                                                   (const __nv_bfloat16*)palo,
                                                   (const __nv_bfloat16*)pwq,
                                                   (float*)pq, QD, Hh, 0);
    gemm_mma2<<<dim3(KVD / 128, MTOK / 128), 256>>>((const __nv_bfloat16*)pahi,
                                                    (const __nv_bfloat16*)palo,
                                                    (const __nv_bfloat16*)pwk,
                                                    (float*)pk, KVD, Hh, 1);
    gemm_mma2<<<dim3(KVD / 128, MTOK / 128), 256>>>((const __nv_bfloat16*)pahi,
                                                    (const __nv_bfloat16*)palo,
                                                    (const __nv_bfloat16*)pwv,
                                                    (float*)pv, KVD, Hh, 2);

    rope_kernel<<<(int)(((size_t)MTOK * NHq * 64 + 255) / 256), 256>>>((float*)pq, NHq, posid);
    rope_kernel<<<(int)(((size_t)MTOK * NKVh * 64 + 255) / 256), 256>>>((float*)pk, NKVh, posid);
    vsplit_kernel<<<(int)(((size_t)Bb * NKVh * HDd * Ss + 255) / 256), 256>>>();

    scores_mma<<<dim3(8, 8, Bb * NHq), 256>>>();
    softmax_kernel<<<Bb * NHq * Ss, 256>>>();
    pv_mma<<<dim3(8, Bb * NHq), 256>>>();

    split2_kernel<<<4096, 256>>>((const float*)pattn, (__nv_bfloat16*)pahi,
                                 (__nv_bfloat16*)palo, nH);
    gemm_mma2<<<dim3(Hh / 128, MTOK / 128), 256>>>((const __nv_bfloat16*)pahi,
                                                   (const __nv_bfloat16*)palo,
                                                   (const __nv_bfloat16*)pwo,
                                                   out, Hh, QD, 3);
}

// round 8
// speedup vs baseline: 2.7705x; 1.1021x over previous
#include <cuda_runtime.h>
#include <cuda_bf16.h>
#include <math.h>
#include <stdint.h>

// Problem constants
constexpr int Bb   = 2;
constexpr int Ss   = 1024;
constexpr int Hh   = 4096;
constexpr int NHq  = 32;
constexpr int NKVh = 8;
constexpr int HDd  = 128;
constexpr int MTOK = Bb * Ss;             // 2048
constexpr int QD   = NHq * HDd;           // 4096
constexpr int KVD  = NKVh * HDd;          // 1024

// ---------------- device scratch (static; allocation-free) ----------------
__device__ float          g_q[(size_t)MTOK * QD];
__device__ float          g_k[(size_t)MTOK * KVD];
__device__ float          g_v[(size_t)MTOK * KVD];
__device__ float          g_attn[(size_t)MTOK * QD];
__device__ float          g_scores[(size_t)Bb * NHq * Ss * Ss];
__device__ __nv_bfloat16  g_ahi[(size_t)MTOK * Hh];
__device__ __nv_bfloat16  g_alo[(size_t)MTOK * Hh];
__device__ __nv_bfloat16  g_wq[(size_t)QD  * Hh];
__device__ __nv_bfloat16  g_wk[(size_t)KVD * Hh];
__device__ __nv_bfloat16  g_wv[(size_t)KVD * Hh];
__device__ __nv_bfloat16  g_wo[(size_t)Hh  * QD];
__device__ __nv_bfloat16  g_vhi[(size_t)Bb * NKVh * HDd * Ss];
__device__ __nv_bfloat16  g_vlo[(size_t)Bb * NKVh * HDd * Ss];
__device__ double         g_absum[4];
__device__ float          g_gamma[4];

// ---------------- helpers ----------------
__device__ __forceinline__ uint32_t smem_u32(const void* p) {
    uint32_t a;
    asm("{ .reg .u64 t; cvta.to.shared.u64 t, %1; cvt.u32.u64 %0, t; }" : "=r"(a) : "l"(p));
    return a;
}
__device__ __forceinline__ uint32_t packbf(float a, float b) {
    __nv_bfloat162 t = __floats2bfloat162_rn(a, b);
    return *(uint32_t*)&t;
}
__device__ __forceinline__ void mma16816(float* c, const uint32_t* a, const uint32_t* b) {
    asm volatile(
        "mma.sync.aligned.m16n8k16.row.col.f32.bf16.bf16.f32 "
        "{%0,%1,%2,%3}, {%4,%5,%6,%7}, {%8,%9}, {%0,%1,%2,%3};"
        : "+f"(c[0]), "+f"(c[1]), "+f"(c[2]), "+f"(c[3])
        : "r"(a[0]), "r"(a[1]), "r"(a[2]), "r"(a[3]), "r"(b[0]), "r"(b[1]));
}
#define CP_ASYNC16(dst, src) \
    asm volatile("cp.async.cg.shared.global [%0], [%1], 16;" :: "r"(dst), "l"(src))
#define CP_COMMIT() asm volatile("cp.async.commit_group;" ::: "memory")
#define CP_WAIT1()  asm volatile("cp.async.wait_group 1;" ::: "memory")
#define CP_WAIT0()  asm volatile("cp.async.wait_group 0;" ::: "memory")

constexpr int ST = 40;   // smem row stride (bf16); 80B rows, conflict-free frag loads

// ---------------- gamma: abs-sum reduction (float4) ----------------
__global__ void init_kernel() {
    if (threadIdx.x < 4) g_absum[threadIdx.x] = 0.0;
}

__global__ void abssum_kernel(const float4* __restrict__ w, size_t n4, int idx) {
    float s = 0.f;
    for (size_t i = (size_t)blockIdx.x * blockDim.x + threadIdx.x; i < n4;
         i += (size_t)gridDim.x * blockDim.x) {
        float4 v = w[i];
        s += fabsf(v.x) + fabsf(v.y) + fabsf(v.z) + fabsf(v.w);
    }
    __shared__ double sh[256];
    sh[threadIdx.x] = (double)s;
    __syncthreads();
    for (int o = 128; o > 0; o >>= 1) {
        if ((int)threadIdx.x < o) sh[threadIdx.x] += sh[threadIdx.x + o];
        __syncthreads();
    }
    if (threadIdx.x == 0) atomicAdd(&g_absum[idx], sh[0]);
}

// ---------------- ternary quantization -> bf16 plane (float4 in) ----------------
__global__ void quantize_kernel(const float4* __restrict__ w,
                                __nv_bfloat162* __restrict__ t, size_t n4, int idx) {
    float gamma = (float)(g_absum[idx] / (double)(n4 * 4)) + 1e-5f;
    if (blockIdx.x == 0 && threadIdx.x == 0) g_gamma[idx] = gamma;
    for (size_t i = (size_t)blockIdx.x * blockDim.x + threadIdx.x; i < n4;
         i += (size_t)gridDim.x * blockDim.x) {
        float4 v = w[i];
        float rx = fminf(1.f, fmaxf(-1.f, rintf(v.x / gamma)));
        float ry = fminf(1.f, fmaxf(-1.f, rintf(v.y / gamma)));
        float rz = fminf(1.f, fmaxf(-1.f, rintf(v.z / gamma)));
        float rw = fminf(1.f, fmaxf(-1.f, rintf(v.w / gamma)));
        t[2 * i]     = __floats2bfloat162_rn(rx, ry);
        t[2 * i + 1] = __floats2bfloat162_rn(rz, rw);
    }
}

// ---------------- fp32 -> (hi,lo) bf16 planes (float4 in) ----------------
__global__ void split2_kernel(const float4* __restrict__ x,
                              __nv_bfloat162* __restrict__ hi,
                              __nv_bfloat162* __restrict__ lo, size_t n4) {
    for (size_t i = (size_t)blockIdx.x * blockDim.x + threadIdx.x; i < n4;
         i += (size_t)gridDim.x * blockDim.x) {
        float4 f = x[i];
        __nv_bfloat162 hxy = __floats2bfloat162_rn(f.x, f.y);
        __nv_bfloat162 hzw = __floats2bfloat162_rn(f.z, f.w);
        hi[2 * i]     = hxy;
        hi[2 * i + 1] = hzw;
        lo[2 * i]     = __floats2bfloat162_rn(f.x - __bfloat162float(hxy.x),
                                              f.y - __bfloat162float(hxy.y));
        lo[2 * i + 1] = __floats2bfloat162_rn(f.z - __bfloat162float(hzw.x),
                                              f.w - __bfloat162float(hzw.y));
    }
}

// ---------------- V -> transposed hi/lo planes: vt[bk][d][s] ----------------
__global__ void vsplit_kernel() {
    size_t idx = (size_t)blockIdx.x * blockDim.x + threadIdx.x;
    if (idx >= (size_t)Bb * NKVh * HDd * Ss) return;
    int s  = (int)(idx & (Ss - 1));
    int d  = (int)((idx >> 10) & 127);
    int bk = (int)(idx >> 17);
    int b  = bk >> 3, kv = bk & 7;
    float v = g_v[((size_t)(b * Ss + s)) * KVD + kv * HDd + d];
    __nv_bfloat16 h = __float2bfloat16_rn(v);
    g_vhi[idx] = h;
    g_vlo[idx] = __float2bfloat16_rn(v - __bfloat162float(h));
}

// ================= cp.async-pipelined projection GEMM =================
// C[M,N] = gamma * (Ahi + Alo)[M,K] . W[N,K]^T; 128x128 tile, K-chunk 32, 2 stages
constexpr int PLANE   = 128 * ST;                 // bf16 elems per smem plane
constexpr int GM_SMEM = 2 * 3 * PLANE * 2;        // bytes = 61440

__global__ __launch_bounds__(256) void gemm_mma2(
    const __nv_bfloat16* __restrict__ Ahi, const __nv_bfloat16* __restrict__ Alo,
    const __nv_bfloat16* __restrict__ W, float* __restrict__ C,
    int N, int K, int gidx)
{
    extern __shared__ __align__(16) __nv_bfloat16 sb[];
    // layout: [stage][plane: 0=Ahi 1=Alo 2=B][128*ST]
    const uint32_t ubase = smem_u32(sb);

    const int tid  = threadIdx.x;
    const int wid  = tid >> 5;
    const int lane = tid & 31;
    const int g    = lane >> 2;
    const int t    = lane & 3;
    const int m0   = blockIdx.y * 128;
    const int n0   = blockIdx.x * 128;
    const int wrow = (wid >> 2) * 64;
    const int wcol = (wid & 3) * 32;

    // per-thread load coords: 512 16B-chunks per plane, 2 per thread
    const int r0 = (tid * 2)     >> 2, c0 = ((tid * 2)     & 3) * 8;
    const int r1 = (tid * 2 + 1) >> 2, c1 = ((tid * 2 + 1) & 3) * 8;

    float acc[4][4][4];
#pragma unroll
    for (int i = 0; i < 4; i++)
#pragma unroll
        for (int j = 0; j < 4; j++)
#pragma unroll
            for (int r = 0; r < 4; r++) acc[i][j][r] = 0.f;

    const int iters = K >> 5;   // K / 32

    auto issue = [&](int it, int stg) {
        const int kc = it << 5;
        uint32_t s0 = ubase + (uint32_t)(stg * 3 * PLANE) * 2;
        CP_ASYNC16(s0 + (r0 * ST + c0) * 2,               &Ahi[(size_t)(m0 + r0) * K + kc + c0]);
        CP_ASYNC16(s0 + (r1 * ST + c1) * 2,               &Ahi[(size_t)(m0 + r1) * K + kc + c1]);
        CP_ASYNC16(s0 + (PLANE + r0 * ST + c0) * 2,       &Alo[(size_t)(m0 + r0) * K + kc + c0]);
        CP_ASYNC16(s0 + (PLANE + r1 * ST + c1) * 2,       &Alo[(size_t)(m0 + r1) * K + kc + c1]);
        CP_ASYNC16(s0 + (2 * PLANE + r0 * ST + c0) * 2,   &W[(size_t)(n0 + r0) * K + kc + c0]);
        CP_ASYNC16(s0 + (2 * PLANE + r1 * ST + c1) * 2,   &W[(size_t)(n0 + r1) * K + kc + c1]);
        CP_COMMIT();
    };

    issue(0, 0);
    for (int it = 0; it < iters; ++it) {
        const int stg = it & 1;
        if (it + 1 < iters) { issue(it + 1, stg ^ 1); CP_WAIT1(); }
        else                { CP_WAIT0(); }
        __syncthreads();

        const __nv_bfloat16* sah = sb + stg * 3 * PLANE;
        const __nv_bfloat16* sal = sah + PLANE;
        const __nv_bfloat16* sbw = sah + 2 * PLANE;

#pragma unroll
        for (int kk = 0; kk < 32; kk += 16) {
            uint32_t ah[4][4], al[4][4], bf[4][2];
#pragma unroll
            for (int mt = 0; mt < 4; mt++) {
                int m = wrow + mt * 16 + g;
                ah[mt][0] = *(const uint32_t*)&sah[(m    ) * ST + kk + 2 * t    ];
                ah[mt][1] = *(const uint32_t*)&sah[(m + 8) * ST + kk + 2 * t    ];
                ah[mt][2] = *(const uint32_t*)&sah[(m    ) * ST + kk + 2 * t + 8];
                ah[mt][3] = *(const uint32_t*)&sah[(m + 8) * ST + kk + 2 * t + 8];
                al[mt][0] = *(const uint32_t*)&sal[(m    ) * ST + kk + 2 * t    ];
                al[mt][1] = *(const uint32_t*)&sal[(m + 8) * ST + kk + 2 * t    ];
                al[mt][2] = *(const uint32_t*)&sal[(m    ) * ST + kk + 2 * t + 8];
                al[mt][3] = *(const uint32_t*)&sal[(m + 8) * ST + kk + 2 * t + 8];
            }
#pragma unroll
            for (int nt = 0; nt < 4; nt++) {
                int n = wcol + nt * 8 + g;
                bf[nt][0] = *(const uint32_t*)&sbw[n * ST + kk + 2 * t    ];
                bf[nt][1] = *(const uint32_t*)&sbw[n * ST + kk + 2 * t + 8];
            }
#pragma unroll
            for (int mt = 0; mt < 4; mt++)
#pragma unroll
                for (int nt = 0; nt < 4; nt++) {
                    mma16816(acc[mt][nt], ah[mt], bf[nt]);
                    mma16816(acc[mt][nt], al[mt], bf[nt]);
                }
        }
        __syncthreads();
    }

    const float gamma = g_gamma[gidx];
#pragma unroll
    for (int mt = 0; mt < 4; mt++) {
#pragma unroll
        for (int nt = 0; nt < 4; nt++) {
            int m = m0 + wrow + mt * 16 + g;
            int n = n0 + wcol + nt * 8 + 2 * t;
            float2 lo = make_float2(acc[mt][nt][0] * gamma, acc[mt][nt][1] * gamma);
            float2 hi = make_float2(acc[mt][nt][2] * gamma, acc[mt][nt][3] * gamma);
            *(float2*)&C[(size_t)m * N + n]       = lo;
            *(float2*)&C[(size_t)(m + 8) * N + n] = hi;
        }
    }
}

// ---------------- RoPE (in place), uses position_ids ----------------
__global__ void rope_kernel(float* __restrict__ x, int nheads,
                            const int* __restrict__ pos_ids) {
    size_t idx = (size_t)blockIdx.x * blockDim.x + threadIdx.x;
    size_t total = (size_t)MTOK * nheads * 64;
    if (idx >= total) return;
    int d = (int)(idx & 63);
    size_t th = idx >> 6;
    int head = (int)(th % nheads);
    size_t tok = th / nheads;
    int pos = pos_ids[tok];
    float inv_freq = 1.0f / powf(10000.0f, (float)d * (1.0f / 64.0f));
    float fr = (float)pos * inv_freq;
    float s, c;
    sincosf(fr, &s, &c);
    float* base = x + tok * ((size_t)nheads * HDd) + (size_t)head * HDd;
    float x1 = base[d], x2 = base[d + 64];
    base[d]      = x1 * c - x2 * s;
    base[d + 64] = x2 * c + x1 * s;
}

// ---------------- scores via HMMA: S = (q.k)/sqrt(HD), lower-tri tiles ----------------
__global__ __launch_bounds__(256) void scores_mma() {
    const int bh = blockIdx.z;
    const int b = bh >> 5, h = bh & 31;
    const int kvh = h >> 2;
    const int m0 = blockIdx.y * 128;
    const int n0 = blockIdx.x * 128;
    if (n0 > m0) return;

    const float* __restrict__ A  = g_q + (size_t)b * Ss * QD  + (size_t)h * HDd;
    const float* __restrict__ Bk = g_k + (size_t)b * Ss * KVD + (size_t)kvh * HDd;
    float* __restrict__ C = g_scores + (size_t)bh * Ss * Ss;

    __shared__ __align__(16) __nv_bfloat16 sqh[128 * ST];
    __shared__ __align__(16) __nv_bfloat16 sql[128 * ST];
    __shared__ __align__(16) __nv_bfloat16 skh[128 * ST];
    __shared__ __align__(16) __nv_bfloat16 skl[128 * ST];

    const int tid  = threadIdx.x;
    const int wid  = tid >> 5;
    const int lane = tid & 31;
    const int g    = lane >> 2;
    const int t    = lane & 3;
    const int wrow = (wid >> 2) * 64;
    const int wcol = (wid & 3) * 32;

    float acc[4][4][4];
#pragma unroll
    for (int i = 0; i < 4; i++)
#pragma unroll
        for (int j = 0; j < 4; j++)
#pragma unroll
            for (int r = 0; r < 4; r++) acc[i][j][r] = 0.f;

    for (int kc = 0; kc < HDd; kc += 32) {
#pragma unroll
        for (int l = 0; l < 4; l++) {
            int seg = tid + l * 256;
            int row = seg >> 3;
            int c4  = (seg & 7) * 4;
            float4 va = *(const float4*)&A[(size_t)(m0 + row) * QD + kc + c4];
            float hx = __bfloat162float(__float2bfloat16_rn(va.x));
            float hy = __bfloat162float(__float2bfloat16_rn(va.y));
            float hz = __bfloat162float(__float2bfloat16_rn(va.z));
            float hw = __bfloat162float(__float2bfloat16_rn(va.w));
            *(uint32_t*)&sqh[row * ST + c4]     = packbf(hx, hy);
            *(uint32_t*)&sqh[row * ST + c4 + 2] = packbf(hz, hw);
            *(uint32_t*)&sql[row * ST + c4]     = packbf(va.x - hx, va.y - hy);
            *(uint32_t*)&sql[row * ST + c4 + 2] = packbf(va.z - hz, va.w - hw);

            float4 vb = *(const float4*)&Bk[(size_t)(n0 + row) * KVD + kc + c4];
            float gx = __bfloat162float(__float2bfloat16_rn(vb.x));
            float gy = __bfloat162float(__float2bfloat16_rn(vb.y));
            float gz = __bfloat162float(__float2bfloat16_rn(vb.z));
            float gw = __bfloat162float(__float2bfloat16_rn(vb.w));
            *(uint32_t*)&skh[row * ST + c4]     = packbf(gx, gy);
            *(uint32_t*)&skh[row * ST + c4 + 2] = packbf(gz, gw);
            *(uint32_t*)&skl[row * ST + c4]     = packbf(vb.x - gx, vb.y - gy);
            *(uint32_t*)&skl[row * ST + c4 + 2] = packbf(vb.z - gz, vb.w - gw);
        }
        __syncthreads();

#pragma unroll
        for (int kk = 0; kk < 32; kk += 16) {
            uint32_t ah[4][4], al[4][4], bh2[4][2], bl2[4][2];
#pragma unroll
            for (int mt = 0; mt < 4; mt++) {
                int m = wrow + mt * 16 + g;
                ah[mt][0] = *(const uint32_t*)&sqh[(m    ) * ST + kk + 2 * t    ];
                ah[mt][1] = *(const uint32_t*)&sqh[(m + 8) * ST + kk + 2 * t    ];
                ah[mt][2] = *(const uint32_t*)&sqh[(m    ) * ST + kk + 2 * t + 8];
                ah[mt][3] = *(const uint32_t*)&sqh[(m + 8) * ST + kk + 2 * t + 8];
                al[mt][0] = *(const uint32_t*)&sql[(m    ) * ST + kk + 2 * t    ];
                al[mt][1] = *(const uint32_t*)&sql[(m + 8) * ST + kk + 2 * t    ];
                al[mt][2] = *(const uint32_t*)&sql[(m    ) * ST + kk + 2 * t + 8];
                al[mt][3] = *(const uint32_t*)&sql[(m + 8) * ST + kk + 2 * t + 8];
            }
#pragma unroll
            for (int nt = 0; nt < 4; nt++) {
                int n = wcol + nt * 8 + g;
                bh2[nt][0] = *(const uint32_t*)&skh[n * ST + kk + 2 * t    ];
                bh2[nt][1] = *(const uint32_t*)&skh[n * ST + kk + 2 * t + 8];
                bl2[nt][0] = *(const uint32_t*)&skl[n * ST + kk + 2 * t    ];
                bl2[nt][1] = *(const uint32_t*)&skl[n * ST + kk + 2 * t + 8];
            }
#pragma unroll
            for (int mt = 0; mt < 4; mt++)
#pragma unroll
                for (int nt = 0; nt < 4; nt++) {
                    mma16816(acc[mt][nt], ah[mt], bh2[nt]);
                    mma16816(acc[mt][nt], al[mt], bh2[nt]);
                    mma16816(acc[mt][nt], ah[mt], bl2[nt]);
                }
        }
        __syncthreads();
    }

    const float scale = 0.08838834764831845f;
#pragma unroll
    for (int mt = 0; mt < 4; mt++) {
#pragma unroll
        for (int nt = 0; nt < 4; nt++) {
            int m = m0 + wrow + mt * 16 + g;
            int n = n0 + wcol + nt * 8 + 2 * t;
            if (n     <= m) C[(size_t)m * Ss + n]     = acc[mt][nt][0] * scale;
            if (n + 1 <= m) C[(size_t)m * Ss + n + 1] = acc[mt][nt][1] * scale;
            int m8 = m + 8;
            if (n     <= m8) C[(size_t)m8 * Ss + n]     = acc[mt][nt][2] * scale;
            if (n + 1 <= m8) C[(size_t)m8 * Ss + n + 1] = acc[mt][nt][3] * scale;
        }
    }
}

// ---------------- row softmax over j<=i, zero-fill j>i ----------------
__global__ void softmax_kernel() {
    const int row = blockIdx.x;
    const int i = row & (Ss - 1);
    float* __restrict__ p = g_scores + (size_t)row * Ss;
    __shared__ float buf[Ss];
    __shared__ float red[40];
    const int len = i + 1;

    float mx = -INFINITY;
    for (int j = threadIdx.x; j < len; j += blockDim.x) {
        float v = p[j]; buf[j] = v; mx = fmaxf(mx, v);
    }
#pragma unroll
    for (int o = 16; o; o >>= 1) mx = fmaxf(mx, __shfl_xor_sync(0xffffffffu, mx, o));
    if ((threadIdx.x & 31) == 0) red[threadIdx.x >> 5] = mx;
    __syncthreads();
    if (threadIdx.x == 0) {
        float m = red[0];
        for (int w = 1; w < 8; w++) m = fmaxf(m, red[w]);
        red[32] = m;
    }
    __syncthreads();
    mx = red[32];

    float sum = 0.f;
    for (int j = threadIdx.x; j < len; j += blockDim.x) {
        float e = expf(buf[j] - mx); buf[j] = e; sum += e;
    }
#pragma unroll
    for (int o = 16; o; o >>= 1) sum += __shfl_xor_sync(0xffffffffu, sum, o);
    __syncthreads();
    if ((threadIdx.x & 31) == 0) red[threadIdx.x >> 5] = sum;
    __syncthreads();
    if (threadIdx.x == 0) {
        float s = red[0];
        for (int w = 1; w < 8; w++) s += red[w];
        red[33] = s;
    }
    __syncthreads();
    const float inv = 1.f / red[33];
    for (int j = threadIdx.x; j < Ss; j += blockDim.x)
        p[j] = (j < len) ? buf[j] * inv : 0.f;
}

// ---------------- PV via HMMA: attn = P @ V (B = V^T planes, causal K-limit) ----------------
__global__ __launch_bounds__(256) void pv_mma() {
    const int bh = blockIdx.y;
    const int b = bh >> 5, h = bh & 31;
    const int kvh = h >> 2;
    const int bk = b * NKVh + kvh;
    const int m0 = blockIdx.x * 128;

    const float* __restrict__ A = g_scores + (size_t)bh * Ss * Ss;
    const __nv_bfloat16* __restrict__ Vh = g_vhi + (size_t)bk * HDd * Ss;
    const __nv_bfloat16* __restrict__ Vl = g_vlo + (size_t)bk * HDd * Ss;
    float* __restrict__ C = g_attn + (size_t)b * Ss * QD + (size_t)h * HDd;

    __shared__ __align__(16) __nv_bfloat16 sph[128 * ST];
    __shared__ __align__(16) __nv_bfloat16 spl[128 * ST];
    __shared__ __align__(16) __nv_bfloat16 svh[128 * ST];
    __shared__ __align__(16) __nv_bfloat16 svl[128 * ST];

    const int tid  = threadIdx.x;
    const int wid  = tid >> 5;
    const int lane = tid & 31;
    const int g    = lane >> 2;
    const int t    = lane & 3;
    const int wrow = (wid >> 2) * 64;
    const int wcol = (wid & 3) * 32;

    float acc[4][4][4];
#pragma unroll
    for (int i = 0; i < 4; i++)
#pragma unroll
        for (int j = 0; j < 4; j++)
#pragma unroll
            for (int r = 0; r < 4; r++) acc[i][j][r] = 0.f;

    const int kmax = m0 + 128;
    for (int kc = 0; kc < kmax; kc += 32) {
#pragma unroll
        for (int l = 0; l < 4; l++) {
            int seg = tid + l * 256;
            int row = seg >> 3;
            int c4  = (seg & 7) * 4;
            float4 va = *(const float4*)&A[(size_t)(m0 + row) * Ss + kc + c4];
            float hx = __bfloat162float(__float2bfloat16_rn(va.x));
            float hy = __bfloat162float(__float2bfloat16_rn(va.y));
            float hz = __bfloat162float(__float2bfloat16_rn(va.z));
            float hw = __bfloat162float(__float2bfloat16_rn(va.w));
            *(uint32_t*)&sph[row * ST + c4]     = packbf(hx, hy);
            *(uint32_t*)&sph[row * ST + c4 + 2] = packbf(hz, hw);
            *(uint32_t*)&spl[row * ST + c4]     = packbf(va.x - hx, va.y - hy);
            *(uint32_t*)&spl[row * ST + c4 + 2] = packbf(va.z - hz, va.w - hw);
        }
#pragma unroll
        for (int l = 0; l < 2; l++) {
            int seg = tid + l * 256;
            int row = seg >> 2;
            int cs  = (seg & 3) * 8;
            *(uint4*)&svh[row * ST + cs] = *(const uint4*)&Vh[(size_t)row * Ss + kc + cs];
            *(uint4*)&svl[row * ST + cs] = *(const uint4*)&Vl[(size_t)row * Ss + kc + cs];
        }
        __syncthreads();

#pragma unroll
        for (int kk = 0; kk < 32; kk += 16) {
            uint32_t ah[4][4], al[4][4], bh2[4][2], bl2[4][2];
#pragma unroll
            for (int mt = 0; mt < 4; mt++) {
                int m = wrow + mt * 16 + g;
                ah[mt][0] = *(const uint32_t*)&sph[(m    ) * ST + kk + 2 * t    ];
                ah[mt][1] = *(const uint32_t*)&sph[(m + 8) * ST + kk + 2 * t    ];
                ah[mt][2] = *(const uint32_t*)&sph[(m    ) * ST + kk + 2 * t + 8];
                ah[mt][3] = *(const uint32_t*)&sph[(m + 8) * ST + kk + 2 * t + 8];
                al[mt][0] = *(const uint32_t*)&spl[(m    ) * ST + kk + 2 * t    ];
                al[mt][1] = *(const uint32_t*)&spl[(m + 8) * ST + kk + 2 * t    ];
                al[mt][2] = *(const uint32_t*)&spl[(m    ) * ST + kk + 2 * t + 8];
                al[mt][3] = *(const uint32_t*)&spl[(m + 8) * ST + kk + 2 * t + 8];
            }
#pragma unroll
            for (int nt = 0; nt < 4; nt++) {
                int n = wcol + nt * 8 + g;
                bh2[nt][0] = *(const uint32_t*)&svh[n * ST + kk + 2 * t    ];
                bh2[nt][1] = *(const uint32_t*)&svh[n * ST + kk + 2 * t + 8];
                bl2[nt][0] = *(const uint32_t*)&svl[n * ST + kk + 2 * t    ];
                bl2[nt][1] = *(const uint32_t*)&svl[n * ST + kk + 2 * t + 8];
            }
#pragma unroll
            for (int mt = 0; mt < 4; mt++)
#pragma unroll
                for (int nt = 0; nt < 4; nt++) {
                    mma16816(acc[mt][nt], ah[mt], bh2[nt]);
                    mma16816(acc[mt][nt], al[mt], bh2[nt]);
                    mma16816(acc[mt][nt], ah[mt], bl2[nt]);
                }
        }
        __syncthreads();
    }

#pragma unroll
    for (int mt = 0; mt < 4; mt++) {
#pragma unroll
        for (int nt = 0; nt < 4; nt++) {
            int m = m0 + wrow + mt * 16 + g;
            int n = wcol + nt * 8 + 2 * t;
            float2 lo = make_float2(acc[mt][nt][0], acc[mt][nt][1]);
            float2 hi = make_float2(acc[mt][nt][2], acc[mt][nt][3]);
            *(float2*)&C[(size_t)m * QD + n]       = lo;
            *(float2*)&C[(size_t)(m + 8) * QD + n] = hi;
        }
    }
}

// ---------------- launch ----------------
extern "C" void kernel_launch(void* const* d_in, const int* in_sizes, int n_in,
                              void* d_out, int out_size)
{
    const float* hidden = nullptr;
    const float* big16[2] = {nullptr, nullptr};
    const float* sml4[2]  = {nullptr, nullptr};
    const int*   posid = nullptr;
    int hidden_idx = -1, nb = 0, ns = 0;
    for (int i = 0; i < n_in; i++) {
        if (in_sizes[i] == 8388608)               { hidden = (const float*)d_in[i]; hidden_idx = i; }
        else if (in_sizes[i] == 16777216 && nb<2) { big16[nb++] = (const float*)d_in[i]; }
        else if (in_sizes[i] == 4194304  && ns<2) { sml4[ns++]  = (const float*)d_in[i]; }
        else if (in_sizes[i] == 2048)             { posid = (const int*)d_in[i]; }
    }
    const float* Wq = (hidden_idx == 0) ? big16[0] : big16[1];
    const float* Wo = (hidden_idx == 0) ? big16[1] : big16[0];
    const float* Wk = sml4[0];
    const float* Wv = sml4[1];
    float* out = (float*)d_out;

    void *pq, *pk, *pv, *pattn, *pahi, *palo, *pwq, *pwk, *pwv, *pwo;
    cudaGetSymbolAddress(&pq, g_q);
    cudaGetSymbolAddress(&pk, g_k);
    cudaGetSymbolAddress(&pv, g_v);
    cudaGetSymbolAddress(&pattn, g_attn);
    cudaGetSymbolAddress(&pahi, g_ahi);
    cudaGetSymbolAddress(&palo, g_alo);
    cudaGetSymbolAddress(&pwq, g_wq);
    cudaGetSymbolAddress(&pwk, g_wk);
    cudaGetSymbolAddress(&pwv, g_wv);
    cudaGetSymbolAddress(&pwo, g_wo);

    cudaFuncSetAttribute(gemm_mma2, cudaFuncAttributeMaxDynamicSharedMemorySize, GM_SMEM);

    const size_t nQ4 = (size_t)QD * Hh / 4;
    const size_t nK4 = (size_t)KVD * Hh / 4;
    const size_t nO4 = (size_t)Hh * QD / 4;
    const size_t nH4 = (size_t)MTOK * Hh / 4;

    init_kernel<<<1, 32>>>();
    abssum_kernel<<<2048, 256>>>((const float4*)Wq, nQ4, 0);
    abssum_kernel<<<2048, 256>>>((const float4*)Wk, nK4, 1);
    abssum_kernel<<<2048, 256>>>((const float4*)Wv, nK4, 2);
    abssum_kernel<<<2048, 256>>>((const float4*)Wo, nO4, 3);

    quantize_kernel<<<4096, 256>>>((const float4*)Wq, (__nv_bfloat162*)pwq, nQ4, 0);
    quantize_kernel<<<4096, 256>>>((const float4*)Wk, (__nv_bfloat162*)pwk, nK4, 1);
    quantize_kernel<<<4096, 256>>>((const float4*)Wv, (__nv_bfloat162*)pwv, nK4, 2);
    quantize_kernel<<<4096, 256>>>((const float4*)Wo, (__nv_bfloat162*)pwo, nO4, 3);

    split2_kernel<<<4096, 256>>>((const float4*)hidden, (__nv_bfloat162*)pahi,
                                 (__nv_bfloat162*)palo, nH4);

    gemm_mma2<<<dim3(QD / 128, MTOK / 128), 256, GM_SMEM>>>(
        (const __nv_bfloat16*)pahi, (const __nv_bfloat16*)palo,
        (const __nv_bfloat16*)pwq, (float*)pq, QD, Hh, 0);
    gemm_mma2<<<dim3(KVD / 128, MTOK / 128), 256, GM_SMEM>>>(
        (const __nv_bfloat16*)pahi, (const __nv_bfloat16*)palo,
        (const __nv_bfloat16*)pwk, (float*)pk, KVD, Hh, 1);
    gemm_mma2<<<dim3(KVD / 128, MTOK / 128), 256, GM_SMEM>>>(
        (const __nv_bfloat16*)pahi, (const __nv_bfloat16*)palo,
        (const __nv_bfloat16*)pwv, (float*)pv, KVD, Hh, 2);

    rope_kernel<<<(int)(((size_t)MTOK * NHq * 64 + 255) / 256), 256>>>((float*)pq, NHq, posid);
    rope_kernel<<<(int)(((size_t)MTOK * NKVh * 64 + 255) / 256), 256>>>((float*)pk, NKVh, posid);
    vsplit_kernel<<<(int)(((size_t)Bb * NKVh * HDd * Ss + 255) / 256), 256>>>();

    scores_mma<<<dim3(8, 8, Bb * NHq), 256>>>();
    softmax_kernel<<<Bb * NHq * Ss, 256>>>();
    pv_mma<<<dim3(8, Bb * NHq), 256>>>();

    split2_kernel<<<4096, 256>>>((const float4*)pattn, (__nv_bfloat162*)pahi,
                                 (__nv_bfloat162*)palo, nH4);
    gemm_mma2<<<dim3(Hh / 128, MTOK / 128), 256, GM_SMEM>>>(
        (const __nv_bfloat16*)pahi, (const __nv_bfloat16*)palo,
        (const __nv_bfloat16*)pwo, out, Hh, QD, 3);
}